// round 2
// baseline (speedup 1.0000x reference)
#include <cuda_runtime.h>
#include <math.h>

#define BATCH 2
#define TSEQ  2048
#define EMB   1024
#define HEADS 16
#define DHEAD 64
#define DFF   4096
#define MROWS 4096   // BATCH*TSEQ

// -------- scratch (static device allocations are the sanctioned path) -------
__device__ float g_xn [(size_t)MROWS * EMB];
__device__ float g_q  [(size_t)BATCH * HEADS * TSEQ * DHEAD];
__device__ float g_k  [(size_t)BATCH * HEADS * TSEQ * DHEAD];
__device__ float g_v  [(size_t)BATCH * HEADS * TSEQ * DHEAD];
__device__ float g_att[(size_t)MROWS * EMB];
__device__ float g_x1 [(size_t)MROWS * EMB];
__device__ float g_h  [(size_t)MROWS * DFF];

// ---------------------------------------------------------------------------
// LayerNorm: one block per row of 1024, 256 threads, float4 per thread
// ---------------------------------------------------------------------------
__global__ __launch_bounds__(256) void ln_kernel(
    const float* __restrict__ in, const float* __restrict__ gamma,
    const float* __restrict__ beta, float* __restrict__ out)
{
    __shared__ float red[16];
    const int tid = threadIdx.x;
    const float* xr = in + (size_t)blockIdx.x * EMB;
    float4 xv = *(const float4*)(xr + tid * 4);

    float s = xv.x + xv.y + xv.z + xv.w;
    #pragma unroll
    for (int o = 16; o > 0; o >>= 1) s += __shfl_xor_sync(0xffffffffu, s, o);
    if ((tid & 31) == 0) red[tid >> 5] = s;
    __syncthreads();
    float tot = 0.f;
    #pragma unroll
    for (int i = 0; i < 8; i++) tot += red[i];
    const float mu = tot * (1.0f / EMB);

    const float dx = xv.x - mu, dy = xv.y - mu, dz = xv.z - mu, dw = xv.w - mu;
    float ss = dx*dx + dy*dy + dz*dz + dw*dw;
    #pragma unroll
    for (int o = 16; o > 0; o >>= 1) ss += __shfl_xor_sync(0xffffffffu, ss, o);
    if ((tid & 31) == 0) red[8 + (tid >> 5)] = ss;
    __syncthreads();
    float vtot = 0.f;
    #pragma unroll
    for (int i = 0; i < 8; i++) vtot += red[8 + i];
    const float inv = rsqrtf(vtot * (1.0f / EMB) + 1e-5f);

    float4 gv = *(const float4*)(gamma + tid * 4);
    float4 bv = *(const float4*)(beta  + tid * 4);
    float4 r;
    r.x = dx * inv * gv.x + bv.x;
    r.y = dy * inv * gv.y + bv.y;
    r.z = dz * inv * gv.z + bv.z;
    r.w = dw * inv * gv.w + bv.w;
    *(float4*)(out + (size_t)blockIdx.x * EMB + tid * 4) = r;
}

// ---------------------------------------------------------------------------
// Generic SGEMM 128x128x8, 256 threads, 8x8 register tiles (4+4 split).
// MODE 0: C = relu(acc + bias)
// MODE 1: C = resid + acc + bias
// ---------------------------------------------------------------------------
template<int MODE>
__global__ __launch_bounds__(256) void sgemm_k(
    const float* __restrict__ A, const float* __restrict__ B,
    const float* __restrict__ bias, const float* __restrict__ resid,
    float* __restrict__ C, int M, int N, int K)
{
    __shared__ float As[8][128];
    __shared__ float Bs[8][128];
    const int tid = threadIdx.x;
    const int bm = blockIdx.x * 128;
    const int bn = blockIdx.y * 128;
    const int tx = tid & 15, ty = tid >> 4;

    float acc[8][8];
    #pragma unroll
    for (int i = 0; i < 8; i++)
        #pragma unroll
        for (int j = 0; j < 8; j++) acc[i][j] = 0.f;

    const int a_row = tid >> 1, a_k = (tid & 1) << 2;
    const int b_k = tid >> 5, b_n = (tid & 31) << 2;
    const float* Aptr = A + (size_t)(bm + a_row) * K + a_k;
    const float* Bptr = B + (size_t)b_k * N + bn + b_n;

    for (int k0 = 0; k0 < K; k0 += 8) {
        float4 av = *(const float4*)(Aptr + k0);
        As[a_k + 0][a_row] = av.x;
        As[a_k + 1][a_row] = av.y;
        As[a_k + 2][a_row] = av.z;
        As[a_k + 3][a_row] = av.w;
        *(float4*)&Bs[b_k][b_n] = *(const float4*)(Bptr + (size_t)k0 * N);
        __syncthreads();

        #pragma unroll
        for (int kk = 0; kk < 8; kk++) {
            float ar[8], br[8];
            *(float4*)&ar[0] = *(float4*)&As[kk][ty * 4];
            *(float4*)&ar[4] = *(float4*)&As[kk][64 + ty * 4];
            *(float4*)&br[0] = *(float4*)&Bs[kk][tx * 4];
            *(float4*)&br[4] = *(float4*)&Bs[kk][64 + tx * 4];
            #pragma unroll
            for (int i = 0; i < 8; i++)
                #pragma unroll
                for (int j = 0; j < 8; j++) acc[i][j] += ar[i] * br[j];
        }
        __syncthreads();
    }

    #pragma unroll
    for (int ib = 0; ib < 2; ib++)
        #pragma unroll
        for (int ii = 0; ii < 4; ii++) {
            const int m = bm + ib * 64 + ty * 4 + ii;
            #pragma unroll
            for (int jb = 0; jb < 2; jb++) {
                const int n = bn + jb * 64 + tx * 4;
                float4 bb = *(const float4*)&bias[n];
                const float* a = &acc[ib * 4 + ii][jb * 4];
                float4 r;
                if (MODE == 0) {
                    r.x = fmaxf(a[0] + bb.x, 0.f);
                    r.y = fmaxf(a[1] + bb.y, 0.f);
                    r.z = fmaxf(a[2] + bb.z, 0.f);
                    r.w = fmaxf(a[3] + bb.w, 0.f);
                } else {
                    float4 rr = *(const float4*)&resid[(size_t)m * N + n];
                    r.x = rr.x + a[0] + bb.x;
                    r.y = rr.y + a[1] + bb.y;
                    r.z = rr.z + a[2] + bb.z;
                    r.w = rr.w + a[3] + bb.w;
                }
                *(float4*)&C[(size_t)m * N + n] = r;
            }
        }
}

// ---------------------------------------------------------------------------
// Fused QKV GEMM: A = xn [4096,1024], per-head weights W* [H,E,DH].
// blockIdx.z selects q/k/v. Output layout [B,H,T,DH].
// ---------------------------------------------------------------------------
__global__ __launch_bounds__(256) void qkv_gemm(
    const float* __restrict__ A,
    const float* __restrict__ Wq, const float* __restrict__ bq,
    const float* __restrict__ Wk, const float* __restrict__ bk,
    const float* __restrict__ Wv, const float* __restrict__ bv,
    float* __restrict__ Oq, float* __restrict__ Ok, float* __restrict__ Ov)
{
    const int z = blockIdx.z;
    const float* W    = (z == 0) ? Wq : (z == 1) ? Wk : Wv;
    const float* bias = (z == 0) ? bq : (z == 1) ? bk : bv;
    float*       O    = (z == 0) ? Oq : (z == 1) ? Ok : Ov;
    const int K = EMB;

    __shared__ float As[8][128];
    __shared__ float Bs[8][128];
    const int tid = threadIdx.x;
    const int bm = blockIdx.x * 128;
    const int bn = blockIdx.y * 128;
    const int tx = tid & 15, ty = tid >> 4;

    float acc[8][8];
    #pragma unroll
    for (int i = 0; i < 8; i++)
        #pragma unroll
        for (int j = 0; j < 8; j++) acc[i][j] = 0.f;

    const int a_row = tid >> 1, a_k = (tid & 1) << 2;
    const int b_k = tid >> 5, b_n = (tid & 31) << 2;
    const float* Aptr = A + (size_t)(bm + a_row) * K + a_k;
    // headed weight: element (k, n) = W[h*K*64 + k*64 + d], h=n>>6, d=n&63
    const int ng = bn + b_n;
    const float* Bptr = W + ((size_t)(ng >> 6) * K) * 64 + (ng & 63);

    for (int k0 = 0; k0 < K; k0 += 8) {
        float4 av = *(const float4*)(Aptr + k0);
        As[a_k + 0][a_row] = av.x;
        As[a_k + 1][a_row] = av.y;
        As[a_k + 2][a_row] = av.z;
        As[a_k + 3][a_row] = av.w;
        *(float4*)&Bs[b_k][b_n] = *(const float4*)(Bptr + (size_t)(k0 + b_k) * 64);
        __syncthreads();

        #pragma unroll
        for (int kk = 0; kk < 8; kk++) {
            float ar[8], br[8];
            *(float4*)&ar[0] = *(float4*)&As[kk][ty * 4];
            *(float4*)&ar[4] = *(float4*)&As[kk][64 + ty * 4];
            *(float4*)&br[0] = *(float4*)&Bs[kk][tx * 4];
            *(float4*)&br[4] = *(float4*)&Bs[kk][64 + tx * 4];
            #pragma unroll
            for (int i = 0; i < 8; i++)
                #pragma unroll
                for (int j = 0; j < 8; j++) acc[i][j] += ar[i] * br[j];
        }
        __syncthreads();
    }

    #pragma unroll
    for (int ib = 0; ib < 2; ib++)
        #pragma unroll
        for (int ii = 0; ii < 4; ii++) {
            const int m = bm + ib * 64 + ty * 4 + ii;
            const int b = m >> 11, t = m & 2047;
            #pragma unroll
            for (int jb = 0; jb < 2; jb++) {
                const int n = bn + jb * 64 + tx * 4;
                const int h = n >> 6, d = n & 63;
                float4 bb = *(const float4*)&bias[n];
                const float* a = &acc[ib * 4 + ii][jb * 4];
                float4 r;
                r.x = a[0] + bb.x; r.y = a[1] + bb.y;
                r.z = a[2] + bb.z; r.w = a[3] + bb.w;
                *(float4*)&O[(((size_t)(b * HEADS + h) * TSEQ + t) << 6) + d] = r;
            }
        }
}

// ---------------------------------------------------------------------------
// Causal flash attention: 64 q-rows per block, 64-wide kv tiles.
// 256 threads: row = tid/4, each quad owns 16 of the 64 dims.
// ---------------------------------------------------------------------------
__global__ __launch_bounds__(256) void attn_kernel(
    const float* __restrict__ q, const float* __restrict__ k,
    const float* __restrict__ v, float* __restrict__ out)
{
    __shared__ float Ks[64][64];
    __shared__ float Vs[64][64];
    const int bh = blockIdx.y;            // b*HEADS + h
    const int b = bh >> 4, h = bh & 15;
    const int qbase = blockIdx.x * 64;
    const float* Q  = q + (size_t)bh * TSEQ * DHEAD;
    const float* Kp = k + (size_t)bh * TSEQ * DHEAD;
    const float* Vp = v + (size_t)bh * TSEQ * DHEAD;
    const int tid = threadIdx.x;
    const int row = tid >> 2, quad = tid & 3;
    const int d0 = quad * 16;
    const int ig = qbase + row;

    float qreg[16];
    #pragma unroll
    for (int c = 0; c < 4; c++)
        *(float4*)&qreg[c * 4] = *(const float4*)&Q[(size_t)ig * DHEAD + d0 + c * 4];

    float o[16];
    #pragma unroll
    for (int i = 0; i < 16; i++) o[i] = 0.f;
    float m_i = -1e30f, l_i = 0.f;
    const float scale = 0.125f;           // 1/sqrt(64)

    const int ntiles = blockIdx.x + 1;    // causal: skip tiles above diagonal
    for (int t0 = 0; t0 < ntiles; t0++) {
        const int kb = t0 * 64;
        __syncthreads();
        #pragma unroll
        for (int c = 0; c < 4; c++) {
            *(float4*)&Ks[row][d0 + c * 4] =
                *(const float4*)&Kp[(size_t)(kb + row) * DHEAD + d0 + c * 4];
            *(float4*)&Vs[row][d0 + c * 4] =
                *(const float4*)&Vp[(size_t)(kb + row) * DHEAD + d0 + c * 4];
        }
        __syncthreads();

        float s[64];
        #pragma unroll
        for (int j = 0; j < 64; j++) {
            float a = 0.f;
            #pragma unroll
            for (int c = 0; c < 4; c++) {
                float4 kv4 = *(const float4*)&Ks[j][d0 + c * 4];
                a += qreg[c*4+0]*kv4.x + qreg[c*4+1]*kv4.y
                   + qreg[c*4+2]*kv4.z + qreg[c*4+3]*kv4.w;
            }
            s[j] = a;
        }
        #pragma unroll
        for (int j = 0; j < 64; j++) {
            s[j] += __shfl_xor_sync(0xffffffffu, s[j], 1);
            s[j] += __shfl_xor_sync(0xffffffffu, s[j], 2);
        }

        float mmax = m_i;
        #pragma unroll
        for (int j = 0; j < 64; j++) {
            s[j] = (kb + j <= ig) ? s[j] * scale : -1e30f;
            mmax = fmaxf(mmax, s[j]);
        }
        const float rescale = __expf(m_i - mmax);
        m_i = mmax;
        float psum = 0.f;
        #pragma unroll
        for (int j = 0; j < 64; j++) {
            float p = __expf(s[j] - mmax);
            s[j] = p;
            psum += p;
        }
        l_i = l_i * rescale + psum;
        #pragma unroll
        for (int c = 0; c < 16; c++) o[c] *= rescale;
        #pragma unroll
        for (int j = 0; j < 64; j++) {
            const float p = s[j];
            #pragma unroll
            for (int c = 0; c < 4; c++) {
                float4 vv = *(const float4*)&Vs[j][d0 + c * 4];
                o[c*4+0] += p * vv.x; o[c*4+1] += p * vv.y;
                o[c*4+2] += p * vv.z; o[c*4+3] += p * vv.w;
            }
        }
    }

    const float inv = 1.0f / l_i;
    const size_t obase = ((size_t)(b * TSEQ + ig)) * EMB + h * DHEAD + d0;
    #pragma unroll
    for (int c = 0; c < 4; c++) {
        float4 r;
        r.x = o[c*4+0] * inv; r.y = o[c*4+1] * inv;
        r.z = o[c*4+2] * inv; r.w = o[c*4+3] * inv;
        *(float4*)&out[obase + c * 4] = r;
    }
}

// ---------------------------------------------------------------------------
static float* sym_addr(const void* symbol)
{
    void* p = nullptr;
    cudaGetSymbolAddress(&p, symbol);
    return (float*)p;
}

extern "C" void kernel_launch(void* const* d_in, const int* in_sizes, int n_in,
                              void* d_out, int out_size)
{
    (void)in_sizes; (void)n_in; (void)out_size;
    const float* x      = (const float*)d_in[0];
    const float* Wq     = (const float*)d_in[1];
    const float* bq     = (const float*)d_in[2];
    const float* Wk     = (const float*)d_in[3];
    const float* bk     = (const float*)d_in[4];
    const float* Wv     = (const float*)d_in[5];
    const float* bv     = (const float*)d_in[6];
    const float* Wo     = (const float*)d_in[7];
    const float* bo     = (const float*)d_in[8];
    const float* W1     = (const float*)d_in[9];
    const float* b1     = (const float*)d_in[10];
    const float* W2     = (const float*)d_in[11];
    const float* b2     = (const float*)d_in[12];
    const float* gamma1 = (const float*)d_in[13];
    const float* beta1  = (const float*)d_in[14];
    const float* gamma2 = (const float*)d_in[15];
    const float* beta2  = (const float*)d_in[16];
    float* out = (float*)d_out;

    float* xn  = sym_addr(g_xn);
    float* qb  = sym_addr(g_q);
    float* kb2 = sym_addr(g_k);
    float* vb2 = sym_addr(g_v);
    float* att = sym_addr(g_att);
    float* x1  = sym_addr(g_x1);
    float* hb  = sym_addr(g_h);

    // 1. LN1
    ln_kernel<<<MROWS, 256>>>(x, gamma1, beta1, xn);
    // 2. QKV projections (fused over heads; z selects q/k/v)
    qkv_gemm<<<dim3(MROWS / 128, EMB / 128, 3), 256>>>(
        xn, Wq, bq, Wk, bk, Wv, bv, qb, kb2, vb2);
    // 3. causal attention -> concat layout [B*T, E]
    attn_kernel<<<dim3(TSEQ / 64, BATCH * HEADS), 256>>>(qb, kb2, vb2, att);
    // 4. output projection + residual: x1 = x + att @ Wo + bo
    sgemm_k<1><<<dim3(MROWS / 128, EMB / 128), 256>>>(
        att, Wo, bo, x, x1, MROWS, EMB, EMB);
    // 5. LN2
    ln_kernel<<<MROWS, 256>>>(x1, gamma2, beta2, xn);
    // 6. FFN1: h = relu(xn @ W1 + b1)
    sgemm_k<0><<<dim3(MROWS / 128, DFF / 128), 256>>>(
        xn, W1, b1, nullptr, hb, MROWS, DFF, EMB);
    // 7. FFN2: out = x1 + h @ W2 + b2
    sgemm_k<1><<<dim3(MROWS / 128, EMB / 128), 256>>>(
        hb, W2, b2, x1, out, MROWS, EMB, DFF);
}

// round 3
// speedup vs baseline: 1.6502x; 1.6502x over previous
#include <cuda_runtime.h>
#include <math.h>

#define BATCH 2
#define TSEQ  2048
#define EMB   1024
#define HEADS 16
#define DHEAD 64
#define DFF   4096
#define MROWS 4096   // BATCH*TSEQ

// -------- scratch --------
__device__ float g_xn [(size_t)MROWS * EMB];
__device__ float g_q  [(size_t)BATCH * HEADS * TSEQ * DHEAD];
__device__ float g_k  [(size_t)BATCH * HEADS * TSEQ * DHEAD];
__device__ float g_v  [(size_t)BATCH * HEADS * TSEQ * DHEAD];
__device__ float g_att[(size_t)MROWS * EMB];
__device__ float g_x1 [(size_t)MROWS * EMB];
__device__ float g_h  [(size_t)MROWS * DFF];

// ---------------------------------------------------------------------------
// LayerNorm (unchanged from R1 — fine)
// ---------------------------------------------------------------------------
__global__ __launch_bounds__(256) void ln_kernel(
    const float* __restrict__ in, const float* __restrict__ gamma,
    const float* __restrict__ beta, float* __restrict__ out)
{
    __shared__ float red[16];
    const int tid = threadIdx.x;
    const float* xr = in + (size_t)blockIdx.x * EMB;
    float4 xv = *(const float4*)(xr + tid * 4);

    float s = xv.x + xv.y + xv.z + xv.w;
    #pragma unroll
    for (int o = 16; o > 0; o >>= 1) s += __shfl_xor_sync(0xffffffffu, s, o);
    if ((tid & 31) == 0) red[tid >> 5] = s;
    __syncthreads();
    float tot = 0.f;
    #pragma unroll
    for (int i = 0; i < 8; i++) tot += red[i];
    const float mu = tot * (1.0f / EMB);

    const float dx = xv.x - mu, dy = xv.y - mu, dz = xv.z - mu, dw = xv.w - mu;
    float ss = dx*dx + dy*dy + dz*dz + dw*dw;
    #pragma unroll
    for (int o = 16; o > 0; o >>= 1) ss += __shfl_xor_sync(0xffffffffu, ss, o);
    if ((tid & 31) == 0) red[8 + (tid >> 5)] = ss;
    __syncthreads();
    float vtot = 0.f;
    #pragma unroll
    for (int i = 0; i < 8; i++) vtot += red[8 + i];
    const float inv = rsqrtf(vtot * (1.0f / EMB) + 1e-5f);

    float4 gv = *(const float4*)(gamma + tid * 4);
    float4 bv = *(const float4*)(beta  + tid * 4);
    float4 r;
    r.x = dx * inv * gv.x + bv.x;
    r.y = dy * inv * gv.y + bv.y;
    r.z = dz * inv * gv.z + bv.z;
    r.w = dw * inv * gv.w + bv.w;
    *(float4*)(out + (size_t)blockIdx.x * EMB + tid * 4) = r;
}

// ---------------------------------------------------------------------------
// TF32 tensor-core GEMM: 128x128x16 tiles, 8 warps (2M x 4N), warp 64x32,
// m16n8k8 mma.sync, double-buffered smem, conflict-free padded layouts.
// MODE 0: C = relu(acc + bias)
// MODE 1: C = resid + acc + bias
// MODE 2: QKV — C = acc + bias, scattered to [B,H,T,DH]
// HEADED: B matrix is per-head weights [H, K, 64] addressed as (k, n=h*64+d)
// ---------------------------------------------------------------------------
__device__ __forceinline__ unsigned f2tf32(float f) {
    unsigned u;
    asm("cvt.rna.tf32.f32 %0, %1;" : "=r"(u) : "f"(f));
    return u;
}

__device__ __forceinline__ void mma_tf32(float* d, const unsigned* a, const unsigned* b) {
    asm volatile(
        "mma.sync.aligned.m16n8k8.row.col.f32.tf32.tf32.f32 "
        "{%0,%1,%2,%3},{%4,%5,%6,%7},{%8,%9},{%0,%1,%2,%3};\n"
        : "+f"(d[0]), "+f"(d[1]), "+f"(d[2]), "+f"(d[3])
        : "r"(a[0]), "r"(a[1]), "r"(a[2]), "r"(a[3]), "r"(b[0]), "r"(b[1]));
}

#define A_STRIDE 20    // 16 + 4 pad: frag-load banks (20g+c)%32 all distinct
#define B_STRIDE 136   // 128 + 8 pad: frag-load banks (8c+g)%32 all distinct

template<int MODE, bool HEADED>
__global__ __launch_bounds__(256) void mma_gemm(
    const float* __restrict__ A, const float* __restrict__ Bg,
    const float* __restrict__ bias, const float* __restrict__ resid,
    float* __restrict__ C, int M, int N, int K)
{
    __shared__ float As[2][128 * A_STRIDE];
    __shared__ float Bs[2][16 * B_STRIDE];

    const int tid  = threadIdx.x;
    const int lane = tid & 31, warp = tid >> 5;
    const int warpM = warp & 1, warpN = warp >> 1;
    const int g = lane >> 2, c = lane & 3;
    const int bm = blockIdx.y * 128, bn = blockIdx.x * 128;

    float acc[64];
    #pragma unroll
    for (int i = 0; i < 64; i++) acc[i] = 0.f;

    // per-thread global load slots
    const int a_row0 = tid >> 2;                 // + 64 for j=1
    const int a_k4   = (tid & 3) << 2;
    const int b_k0   = tid >> 5;                 // + 8 for j=1
    const int b_n4   = (tid & 31) << 2;

    float4 a_ld[2], b_ld[2];

    auto gload = [&](int t) {
        const int k0 = t * 16;
        #pragma unroll
        for (int j = 0; j < 2; j++) {
            const int row = a_row0 + j * 64;
            a_ld[j] = *(const float4*)&A[(size_t)(bm + row) * K + k0 + a_k4];
        }
        #pragma unroll
        for (int j = 0; j < 2; j++) {
            const int kk = k0 + b_k0 + j * 8;
            const int n  = bn + b_n4;
            const float* src = HEADED
                ? Bg + (((size_t)(n >> 6)) * K + kk) * 64 + (n & 63)
                : Bg + (size_t)kk * N + n;
            b_ld[j] = *(const float4*)src;
        }
    };
    auto sstore = [&](int buf) {
        #pragma unroll
        for (int j = 0; j < 2; j++) {
            const int row = a_row0 + j * 64;
            float* p = &As[buf][row * A_STRIDE + a_k4];
            p[0] = __uint_as_float(f2tf32(a_ld[j].x));
            p[1] = __uint_as_float(f2tf32(a_ld[j].y));
            p[2] = __uint_as_float(f2tf32(a_ld[j].z));
            p[3] = __uint_as_float(f2tf32(a_ld[j].w));
        }
        #pragma unroll
        for (int j = 0; j < 2; j++) {
            const int kk = b_k0 + j * 8;
            float* p = &Bs[buf][kk * B_STRIDE + b_n4];
            p[0] = __uint_as_float(f2tf32(b_ld[j].x));
            p[1] = __uint_as_float(f2tf32(b_ld[j].y));
            p[2] = __uint_as_float(f2tf32(b_ld[j].z));
            p[3] = __uint_as_float(f2tf32(b_ld[j].w));
        }
    };

    const int ntile = K >> 4;
    gload(0);
    sstore(0);
    __syncthreads();

    for (int t = 0; t < ntile; ++t) {
        const int cur = t & 1;
        if (t + 1 < ntile) gload(t + 1);

        #pragma unroll
        for (int ks = 0; ks < 2; ++ks) {
            unsigned af[4][4], bf[4][2];
            #pragma unroll
            for (int mt = 0; mt < 4; mt++) {
                const int r = warpM * 64 + mt * 16 + g;
                const int kc = ks * 8 + c;
                af[mt][0] = __float_as_uint(As[cur][r * A_STRIDE + kc]);
                af[mt][1] = __float_as_uint(As[cur][(r + 8) * A_STRIDE + kc]);
                af[mt][2] = __float_as_uint(As[cur][r * A_STRIDE + kc + 4]);
                af[mt][3] = __float_as_uint(As[cur][(r + 8) * A_STRIDE + kc + 4]);
            }
            #pragma unroll
            for (int nt = 0; nt < 4; nt++) {
                const int col = warpN * 32 + nt * 8 + g;
                bf[nt][0] = __float_as_uint(Bs[cur][(ks * 8 + c) * B_STRIDE + col]);
                bf[nt][1] = __float_as_uint(Bs[cur][(ks * 8 + c + 4) * B_STRIDE + col]);
            }
            #pragma unroll
            for (int mt = 0; mt < 4; mt++)
                #pragma unroll
                for (int nt = 0; nt < 4; nt++)
                    mma_tf32(&acc[(mt * 4 + nt) * 4], af[mt], bf[nt]);
        }

        if (t + 1 < ntile) {
            sstore((t + 1) & 1);
            __syncthreads();
        }
    }

    // ---- epilogue ----
    #pragma unroll
    for (int mt = 0; mt < 4; mt++) {
        const int r0 = bm + warpM * 64 + mt * 16 + g;
        const int r1 = r0 + 8;
        #pragma unroll
        for (int nt = 0; nt < 4; nt++) {
            const int nn = bn + warpN * 32 + nt * 8 + 2 * c;
            const float* a = &acc[(mt * 4 + nt) * 4];
            float2 bb = *(const float2*)&bias[nn];
            float v00 = a[0] + bb.x, v01 = a[1] + bb.y;
            float v10 = a[2] + bb.x, v11 = a[3] + bb.y;
            if (MODE == 0) {
                v00 = fmaxf(v00, 0.f); v01 = fmaxf(v01, 0.f);
                v10 = fmaxf(v10, 0.f); v11 = fmaxf(v11, 0.f);
                *(float2*)&C[(size_t)r0 * N + nn] = make_float2(v00, v01);
                *(float2*)&C[(size_t)r1 * N + nn] = make_float2(v10, v11);
            } else if (MODE == 1) {
                float2 rr0 = *(const float2*)&resid[(size_t)r0 * N + nn];
                float2 rr1 = *(const float2*)&resid[(size_t)r1 * N + nn];
                *(float2*)&C[(size_t)r0 * N + nn] = make_float2(v00 + rr0.x, v01 + rr0.y);
                *(float2*)&C[(size_t)r1 * N + nn] = make_float2(v10 + rr1.x, v11 + rr1.y);
            } else {
                // QKV scatter: row m -> (b,t), col n -> (h,d); out [B,H,T,DH]
                const int h = nn >> 6, d = nn & 63;
                const int b0 = r0 >> 11, t0i = r0 & 2047;
                const int b1 = r1 >> 11, t1i = r1 & 2047;
                *(float2*)&C[((((size_t)(b0 * HEADS + h)) * TSEQ + t0i) << 6) + d] =
                    make_float2(v00, v01);
                *(float2*)&C[((((size_t)(b1 * HEADS + h)) * TSEQ + t1i) << 6) + d] =
                    make_float2(v10, v11);
            }
        }
    }
}

// ---------------------------------------------------------------------------
// Causal flash attention (unchanged from R1)
// ---------------------------------------------------------------------------
__global__ __launch_bounds__(256) void attn_kernel(
    const float* __restrict__ q, const float* __restrict__ k,
    const float* __restrict__ v, float* __restrict__ out)
{
    __shared__ float Ks[64][64];
    __shared__ float Vs[64][64];
    const int bh = blockIdx.y;
    const int b = bh >> 4, h = bh & 15;
    const int qbase = blockIdx.x * 64;
    const float* Q  = q + (size_t)bh * TSEQ * DHEAD;
    const float* Kp = k + (size_t)bh * TSEQ * DHEAD;
    const float* Vp = v + (size_t)bh * TSEQ * DHEAD;
    const int tid = threadIdx.x;
    const int row = tid >> 2, quad = tid & 3;
    const int d0 = quad * 16;
    const int ig = qbase + row;

    float qreg[16];
    #pragma unroll
    for (int c = 0; c < 4; c++)
        *(float4*)&qreg[c * 4] = *(const float4*)&Q[(size_t)ig * DHEAD + d0 + c * 4];

    float o[16];
    #pragma unroll
    for (int i = 0; i < 16; i++) o[i] = 0.f;
    float m_i = -1e30f, l_i = 0.f;
    const float scale = 0.125f;

    const int ntiles = blockIdx.x + 1;
    for (int t0 = 0; t0 < ntiles; t0++) {
        const int kb = t0 * 64;
        __syncthreads();
        #pragma unroll
        for (int c = 0; c < 4; c++) {
            *(float4*)&Ks[row][d0 + c * 4] =
                *(const float4*)&Kp[(size_t)(kb + row) * DHEAD + d0 + c * 4];
            *(float4*)&Vs[row][d0 + c * 4] =
                *(const float4*)&Vp[(size_t)(kb + row) * DHEAD + d0 + c * 4];
        }
        __syncthreads();

        float s[64];
        #pragma unroll
        for (int j = 0; j < 64; j++) {
            float a = 0.f;
            #pragma unroll
            for (int c = 0; c < 4; c++) {
                float4 kv4 = *(const float4*)&Ks[j][d0 + c * 4];
                a += qreg[c*4+0]*kv4.x + qreg[c*4+1]*kv4.y
                   + qreg[c*4+2]*kv4.z + qreg[c*4+3]*kv4.w;
            }
            s[j] = a;
        }
        #pragma unroll
        for (int j = 0; j < 64; j++) {
            s[j] += __shfl_xor_sync(0xffffffffu, s[j], 1);
            s[j] += __shfl_xor_sync(0xffffffffu, s[j], 2);
        }

        float mmax = m_i;
        #pragma unroll
        for (int j = 0; j < 64; j++) {
            s[j] = (kb + j <= ig) ? s[j] * scale : -1e30f;
            mmax = fmaxf(mmax, s[j]);
        }
        const float rescale = __expf(m_i - mmax);
        m_i = mmax;
        float psum = 0.f;
        #pragma unroll
        for (int j = 0; j < 64; j++) {
            float p = __expf(s[j] - mmax);
            s[j] = p;
            psum += p;
        }
        l_i = l_i * rescale + psum;
        #pragma unroll
        for (int c = 0; c < 16; c++) o[c] *= rescale;
        #pragma unroll
        for (int j = 0; j < 64; j++) {
            const float p = s[j];
            #pragma unroll
            for (int c = 0; c < 4; c++) {
                float4 vv = *(const float4*)&Vs[j][d0 + c * 4];
                o[c*4+0] += p * vv.x; o[c*4+1] += p * vv.y;
                o[c*4+2] += p * vv.z; o[c*4+3] += p * vv.w;
            }
        }
    }

    const float inv = 1.0f / l_i;
    const size_t obase = ((size_t)(b * TSEQ + ig)) * EMB + h * DHEAD + d0;
    #pragma unroll
    for (int c = 0; c < 4; c++) {
        float4 r;
        r.x = o[c*4+0] * inv; r.y = o[c*4+1] * inv;
        r.z = o[c*4+2] * inv; r.w = o[c*4+3] * inv;
        *(float4*)&out[obase + c * 4] = r;
    }
}

// ---------------------------------------------------------------------------
static float* sym_addr(const void* symbol)
{
    void* p = nullptr;
    cudaGetSymbolAddress(&p, symbol);
    return (float*)p;
}

extern "C" void kernel_launch(void* const* d_in, const int* in_sizes, int n_in,
                              void* d_out, int out_size)
{
    (void)in_sizes; (void)n_in; (void)out_size;
    const float* x      = (const float*)d_in[0];
    const float* Wq     = (const float*)d_in[1];
    const float* bq     = (const float*)d_in[2];
    const float* Wk     = (const float*)d_in[3];
    const float* bk     = (const float*)d_in[4];
    const float* Wv     = (const float*)d_in[5];
    const float* bv     = (const float*)d_in[6];
    const float* Wo     = (const float*)d_in[7];
    const float* bo     = (const float*)d_in[8];
    const float* W1     = (const float*)d_in[9];
    const float* b1     = (const float*)d_in[10];
    const float* W2     = (const float*)d_in[11];
    const float* b2     = (const float*)d_in[12];
    const float* gamma1 = (const float*)d_in[13];
    const float* beta1  = (const float*)d_in[14];
    const float* gamma2 = (const float*)d_in[15];
    const float* beta2  = (const float*)d_in[16];
    float* out = (float*)d_out;

    float* xn  = sym_addr(g_xn);
    float* qb  = sym_addr(g_q);
    float* kb2 = sym_addr(g_k);
    float* vb2 = sym_addr(g_v);
    float* att = sym_addr(g_att);
    float* x1  = sym_addr(g_x1);
    float* hb  = sym_addr(g_h);

    // 1. LN1
    ln_kernel<<<MROWS, 256>>>(x, gamma1, beta1, xn);
    // 2. QKV projections (TF32 mma, headed weights, scattered output)
    mma_gemm<2, true><<<dim3(EMB / 128, MROWS / 128), 256>>>(
        xn, Wq, bq, nullptr, qb, MROWS, EMB, EMB);
    mma_gemm<2, true><<<dim3(EMB / 128, MROWS / 128), 256>>>(
        xn, Wk, bk, nullptr, kb2, MROWS, EMB, EMB);
    mma_gemm<2, true><<<dim3(EMB / 128, MROWS / 128), 256>>>(
        xn, Wv, bv, nullptr, vb2, MROWS, EMB, EMB);
    // 3. causal attention -> concat layout [B*T, E]
    attn_kernel<<<dim3(TSEQ / 64, BATCH * HEADS), 256>>>(qb, kb2, vb2, att);
    // 4. output projection + residual
    mma_gemm<1, false><<<dim3(EMB / 128, MROWS / 128), 256>>>(
        att, Wo, bo, x, x1, MROWS, EMB, EMB);
    // 5. LN2
    ln_kernel<<<MROWS, 256>>>(x1, gamma2, beta2, xn);
    // 6. FFN1
    mma_gemm<0, false><<<dim3(DFF / 128, MROWS / 128), 256>>>(
        xn, W1, b1, nullptr, hb, MROWS, DFF, EMB);
    // 7. FFN2 + residual -> out
    mma_gemm<1, false><<<dim3(EMB / 128, MROWS / 128), 256>>>(
        hb, W2, b2, x1, out, MROWS, EMB, DFF);
}

// round 4
// speedup vs baseline: 4.9051x; 2.9724x over previous
#include <cuda_runtime.h>
#include <math.h>

#define BATCH 2
#define TSEQ  2048
#define EMB   1024
#define HEADS 16
#define DHEAD 64
#define DFF   4096
#define MROWS 4096   // BATCH*TSEQ

// -------- scratch --------
__device__ float g_xn [(size_t)MROWS * EMB];
__device__ float g_q  [(size_t)BATCH * HEADS * TSEQ * DHEAD];
__device__ float g_k  [(size_t)BATCH * HEADS * TSEQ * DHEAD];
__device__ float g_v  [(size_t)BATCH * HEADS * TSEQ * DHEAD];
__device__ float g_att[(size_t)MROWS * EMB];
__device__ float g_x1 [(size_t)MROWS * EMB];
__device__ float g_h  [(size_t)MROWS * DFF];

__device__ __forceinline__ unsigned f2tf32(float f) {
    unsigned u;
    asm("cvt.rna.tf32.f32 %0, %1;" : "=r"(u) : "f"(f));
    return u;
}

__device__ __forceinline__ void mma_tf32(float* d, const unsigned* a, const unsigned* b) {
    asm volatile(
        "mma.sync.aligned.m16n8k8.row.col.f32.tf32.tf32.f32 "
        "{%0,%1,%2,%3},{%4,%5,%6,%7},{%8,%9},{%0,%1,%2,%3};\n"
        : "+f"(d[0]), "+f"(d[1]), "+f"(d[2]), "+f"(d[3])
        : "r"(a[0]), "r"(a[1]), "r"(a[2]), "r"(a[3]), "r"(b[0]), "r"(b[1]));
}

// ---------------------------------------------------------------------------
// LayerNorm
// ---------------------------------------------------------------------------
__global__ __launch_bounds__(256) void ln_kernel(
    const float* __restrict__ in, const float* __restrict__ gamma,
    const float* __restrict__ beta, float* __restrict__ out)
{
    __shared__ float red[16];
    const int tid = threadIdx.x;
    const float* xr = in + (size_t)blockIdx.x * EMB;
    float4 xv = *(const float4*)(xr + tid * 4);

    float s = xv.x + xv.y + xv.z + xv.w;
    #pragma unroll
    for (int o = 16; o > 0; o >>= 1) s += __shfl_xor_sync(0xffffffffu, s, o);
    if ((tid & 31) == 0) red[tid >> 5] = s;
    __syncthreads();
    float tot = 0.f;
    #pragma unroll
    for (int i = 0; i < 8; i++) tot += red[i];
    const float mu = tot * (1.0f / EMB);

    const float dx = xv.x - mu, dy = xv.y - mu, dz = xv.z - mu, dw = xv.w - mu;
    float ss = dx*dx + dy*dy + dz*dz + dw*dw;
    #pragma unroll
    for (int o = 16; o > 0; o >>= 1) ss += __shfl_xor_sync(0xffffffffu, ss, o);
    if ((tid & 31) == 0) red[8 + (tid >> 5)] = ss;
    __syncthreads();
    float vtot = 0.f;
    #pragma unroll
    for (int i = 0; i < 8; i++) vtot += red[8 + i];
    const float inv = rsqrtf(vtot * (1.0f / EMB) + 1e-5f);

    float4 gv = *(const float4*)(gamma + tid * 4);
    float4 bv = *(const float4*)(beta  + tid * 4);
    float4 r;
    r.x = dx * inv * gv.x + bv.x;
    r.y = dy * inv * gv.y + bv.y;
    r.z = dz * inv * gv.z + bv.z;
    r.w = dw * inv * gv.w + bv.w;
    *(float4*)(out + (size_t)blockIdx.x * EMB + tid * 4) = r;
}

// ---------------------------------------------------------------------------
// TF32 tensor-core GEMM (unchanged from R2)
// ---------------------------------------------------------------------------
#define A_STRIDE 20
#define B_STRIDE 136

template<int MODE, bool HEADED>
__global__ __launch_bounds__(256) void mma_gemm(
    const float* __restrict__ A, const float* __restrict__ Bg,
    const float* __restrict__ bias, const float* __restrict__ resid,
    float* __restrict__ C, int M, int N, int K)
{
    __shared__ float As[2][128 * A_STRIDE];
    __shared__ float Bs[2][16 * B_STRIDE];

    const int tid  = threadIdx.x;
    const int lane = tid & 31, warp = tid >> 5;
    const int warpM = warp & 1, warpN = warp >> 1;
    const int g = lane >> 2, c = lane & 3;
    const int bm = blockIdx.y * 128, bn = blockIdx.x * 128;

    float acc[64];
    #pragma unroll
    for (int i = 0; i < 64; i++) acc[i] = 0.f;

    const int a_row0 = tid >> 2;
    const int a_k4   = (tid & 3) << 2;
    const int b_k0   = tid >> 5;
    const int b_n4   = (tid & 31) << 2;

    float4 a_ld[2], b_ld[2];

    auto gload = [&](int t) {
        const int k0 = t * 16;
        #pragma unroll
        for (int j = 0; j < 2; j++) {
            const int row = a_row0 + j * 64;
            a_ld[j] = *(const float4*)&A[(size_t)(bm + row) * K + k0 + a_k4];
        }
        #pragma unroll
        for (int j = 0; j < 2; j++) {
            const int kk = k0 + b_k0 + j * 8;
            const int n  = bn + b_n4;
            const float* src = HEADED
                ? Bg + (((size_t)(n >> 6)) * K + kk) * 64 + (n & 63)
                : Bg + (size_t)kk * N + n;
            b_ld[j] = *(const float4*)src;
        }
    };
    auto sstore = [&](int buf) {
        #pragma unroll
        for (int j = 0; j < 2; j++) {
            const int row = a_row0 + j * 64;
            float* p = &As[buf][row * A_STRIDE + a_k4];
            p[0] = __uint_as_float(f2tf32(a_ld[j].x));
            p[1] = __uint_as_float(f2tf32(a_ld[j].y));
            p[2] = __uint_as_float(f2tf32(a_ld[j].z));
            p[3] = __uint_as_float(f2tf32(a_ld[j].w));
        }
        #pragma unroll
        for (int j = 0; j < 2; j++) {
            const int kk = b_k0 + j * 8;
            float* p = &Bs[buf][kk * B_STRIDE + b_n4];
            p[0] = __uint_as_float(f2tf32(b_ld[j].x));
            p[1] = __uint_as_float(f2tf32(b_ld[j].y));
            p[2] = __uint_as_float(f2tf32(b_ld[j].z));
            p[3] = __uint_as_float(f2tf32(b_ld[j].w));
        }
    };

    const int ntile = K >> 4;
    gload(0);
    sstore(0);
    __syncthreads();

    for (int t = 0; t < ntile; ++t) {
        const int cur = t & 1;
        if (t + 1 < ntile) gload(t + 1);

        #pragma unroll
        for (int ks = 0; ks < 2; ++ks) {
            unsigned af[4][4], bf[4][2];
            #pragma unroll
            for (int mt = 0; mt < 4; mt++) {
                const int r = warpM * 64 + mt * 16 + g;
                const int kc = ks * 8 + c;
                af[mt][0] = __float_as_uint(As[cur][r * A_STRIDE + kc]);
                af[mt][1] = __float_as_uint(As[cur][(r + 8) * A_STRIDE + kc]);
                af[mt][2] = __float_as_uint(As[cur][r * A_STRIDE + kc + 4]);
                af[mt][3] = __float_as_uint(As[cur][(r + 8) * A_STRIDE + kc + 4]);
            }
            #pragma unroll
            for (int nt = 0; nt < 4; nt++) {
                const int col = warpN * 32 + nt * 8 + g;
                bf[nt][0] = __float_as_uint(Bs[cur][(ks * 8 + c) * B_STRIDE + col]);
                bf[nt][1] = __float_as_uint(Bs[cur][(ks * 8 + c + 4) * B_STRIDE + col]);
            }
            #pragma unroll
            for (int mt = 0; mt < 4; mt++)
                #pragma unroll
                for (int nt = 0; nt < 4; nt++)
                    mma_tf32(&acc[(mt * 4 + nt) * 4], af[mt], bf[nt]);
        }

        if (t + 1 < ntile) {
            sstore((t + 1) & 1);
            __syncthreads();
        }
    }

    #pragma unroll
    for (int mt = 0; mt < 4; mt++) {
        const int r0 = bm + warpM * 64 + mt * 16 + g;
        const int r1 = r0 + 8;
        #pragma unroll
        for (int nt = 0; nt < 4; nt++) {
            const int nn = bn + warpN * 32 + nt * 8 + 2 * c;
            const float* a = &acc[(mt * 4 + nt) * 4];
            float2 bb = *(const float2*)&bias[nn];
            float v00 = a[0] + bb.x, v01 = a[1] + bb.y;
            float v10 = a[2] + bb.x, v11 = a[3] + bb.y;
            if (MODE == 0) {
                v00 = fmaxf(v00, 0.f); v01 = fmaxf(v01, 0.f);
                v10 = fmaxf(v10, 0.f); v11 = fmaxf(v11, 0.f);
                *(float2*)&C[(size_t)r0 * N + nn] = make_float2(v00, v01);
                *(float2*)&C[(size_t)r1 * N + nn] = make_float2(v10, v11);
            } else if (MODE == 1) {
                float2 rr0 = *(const float2*)&resid[(size_t)r0 * N + nn];
                float2 rr1 = *(const float2*)&resid[(size_t)r1 * N + nn];
                *(float2*)&C[(size_t)r0 * N + nn] = make_float2(v00 + rr0.x, v01 + rr0.y);
                *(float2*)&C[(size_t)r1 * N + nn] = make_float2(v10 + rr1.x, v11 + rr1.y);
            } else {
                const int h = nn >> 6, d = nn & 63;
                const int b0 = r0 >> 11, t0i = r0 & 2047;
                const int b1 = r1 >> 11, t1i = r1 & 2047;
                *(float2*)&C[((((size_t)(b0 * HEADS + h)) * TSEQ + t0i) << 6) + d] =
                    make_float2(v00, v01);
                *(float2*)&C[((((size_t)(b1 * HEADS + h)) * TSEQ + t1i) << 6) + d] =
                    make_float2(v10, v11);
            }
        }
    }
}

// ---------------------------------------------------------------------------
// TF32 tensor-core causal flash attention.
// 64 q-rows per block, 4 warps (one m16 strip each), kv tiles of 64.
// Ps (exp'd probabilities) overlays Ks after QK^T is done.
// ---------------------------------------------------------------------------
__global__ __launch_bounds__(128) void attn_mma(
    const float* __restrict__ q, const float* __restrict__ k,
    const float* __restrict__ v, float* __restrict__ out)
{
    __shared__ float Ks[64][68];   // doubles as Ps after QK^T
    __shared__ float Vs[64][68];

    const int bh = blockIdx.y;
    const int b = bh >> 4, h = bh & 15;
    const int qt = blockIdx.x;
    const int qbase = qt * 64;
    const float* Q  = q + (size_t)bh * TSEQ * DHEAD;
    const float* Kp = k + (size_t)bh * TSEQ * DHEAD;
    const float* Vp = v + (size_t)bh * TSEQ * DHEAD;

    const int tid = threadIdx.x;
    const int lane = tid & 31, w = tid >> 5;
    const int g = lane >> 2, c = lane & 3;
    const int r0 = w * 16 + g;   // this thread's local q rows: r0, r0+8

    // Q fragments, softmax scale (1/8, exact) folded in
    unsigned qf[8][4];
    #pragma unroll
    for (int ks = 0; ks < 8; ks++) {
        const int kc = ks * 8;
        qf[ks][0] = f2tf32(0.125f * Q[(size_t)(qbase + r0)     * 64 + kc + c]);
        qf[ks][1] = f2tf32(0.125f * Q[(size_t)(qbase + r0 + 8) * 64 + kc + c]);
        qf[ks][2] = f2tf32(0.125f * Q[(size_t)(qbase + r0)     * 64 + kc + c + 4]);
        qf[ks][3] = f2tf32(0.125f * Q[(size_t)(qbase + r0 + 8) * 64 + kc + c + 4]);
    }

    float oacc[8][4];
    #pragma unroll
    for (int i = 0; i < 8; i++)
        #pragma unroll
        for (int j = 0; j < 4; j++) oacc[i][j] = 0.f;
    float m0 = -1e30f, m1 = -1e30f, l0 = 0.f, l1 = 0.f;

    for (int t = 0; t <= qt; t++) {
        const int kb = t * 64;
        __syncthreads();   // previous tile fully consumed
        // load K, V tiles (tf32-converted)
        #pragma unroll
        for (int i = 0; i < 8; i++) {
            const int idx = i * 128 + tid;          // 0..1023
            const int row = idx >> 4, col = (idx & 15) << 2;
            float4 kv = *(const float4*)&Kp[(size_t)(kb + row) * 64 + col];
            float4 vv = *(const float4*)&Vp[(size_t)(kb + row) * 64 + col];
            float4 ko, vo;
            ko.x = __uint_as_float(f2tf32(kv.x)); ko.y = __uint_as_float(f2tf32(kv.y));
            ko.z = __uint_as_float(f2tf32(kv.z)); ko.w = __uint_as_float(f2tf32(kv.w));
            vo.x = __uint_as_float(f2tf32(vv.x)); vo.y = __uint_as_float(f2tf32(vv.y));
            vo.z = __uint_as_float(f2tf32(vv.z)); vo.w = __uint_as_float(f2tf32(vv.w));
            *(float4*)&Ks[row][col] = ko;
            *(float4*)&Vs[row][col] = vo;
        }
        __syncthreads();

        // S = Q @ K^T (scale pre-folded)
        float sacc[8][4];
        #pragma unroll
        for (int i = 0; i < 8; i++)
            #pragma unroll
            for (int j = 0; j < 4; j++) sacc[i][j] = 0.f;
        #pragma unroll
        for (int ks = 0; ks < 8; ks++) {
            const int kc = ks * 8;
            #pragma unroll
            for (int nt = 0; nt < 8; nt++) {
                unsigned bf[2];
                bf[0] = __float_as_uint(Ks[nt * 8 + g][kc + c]);
                bf[1] = __float_as_uint(Ks[nt * 8 + g][kc + c + 4]);
                mma_tf32(sacc[nt], qf[ks], bf);
            }
        }
        __syncthreads();   // Ks reads done everywhere; safe to overlay Ps

        // causal mask (only diagonal tile is partial)
        if (t == qt) {
            #pragma unroll
            for (int nt = 0; nt < 8; nt++) {
                const int c0 = nt * 8 + 2 * c, c1 = c0 + 1;
                if (c0 > r0)     sacc[nt][0] = -1e30f;
                if (c1 > r0)     sacc[nt][1] = -1e30f;
                if (c0 > r0 + 8) sacc[nt][2] = -1e30f;
                if (c1 > r0 + 8) sacc[nt][3] = -1e30f;
            }
        }

        // online softmax (rows r0 and r0+8)
        float mx0 = m0, mx1 = m1;
        #pragma unroll
        for (int nt = 0; nt < 8; nt++) {
            mx0 = fmaxf(mx0, fmaxf(sacc[nt][0], sacc[nt][1]));
            mx1 = fmaxf(mx1, fmaxf(sacc[nt][2], sacc[nt][3]));
        }
        #pragma unroll
        for (int o = 1; o <= 2; o <<= 1) {
            mx0 = fmaxf(mx0, __shfl_xor_sync(0xffffffffu, mx0, o));
            mx1 = fmaxf(mx1, __shfl_xor_sync(0xffffffffu, mx1, o));
        }
        const float rs0 = __expf(m0 - mx0), rs1 = __expf(m1 - mx1);
        m0 = mx0; m1 = mx1;

        float (*Ps)[68] = Ks;   // overlay
        float sum0 = 0.f, sum1 = 0.f;
        #pragma unroll
        for (int nt = 0; nt < 8; nt++) {
            const int cc = nt * 8 + 2 * c;
            float p00 = __expf(sacc[nt][0] - mx0);
            float p01 = __expf(sacc[nt][1] - mx0);
            float p10 = __expf(sacc[nt][2] - mx1);
            float p11 = __expf(sacc[nt][3] - mx1);
            sum0 += p00 + p01;
            sum1 += p10 + p11;
            *(float2*)&Ps[r0][cc] = make_float2(
                __uint_as_float(f2tf32(p00)), __uint_as_float(f2tf32(p01)));
            *(float2*)&Ps[r0 + 8][cc] = make_float2(
                __uint_as_float(f2tf32(p10)), __uint_as_float(f2tf32(p11)));
        }
        #pragma unroll
        for (int o = 1; o <= 2; o <<= 1) {
            sum0 += __shfl_xor_sync(0xffffffffu, sum0, o);
            sum1 += __shfl_xor_sync(0xffffffffu, sum1, o);
        }
        l0 = l0 * rs0 + sum0;
        l1 = l1 * rs1 + sum1;
        #pragma unroll
        for (int nt = 0; nt < 8; nt++) {
            oacc[nt][0] *= rs0; oacc[nt][1] *= rs0;
            oacc[nt][2] *= rs1; oacc[nt][3] *= rs1;
        }
        __syncwarp();   // Ps rows of this warp visible to this warp's LDS

        // O += P @ V
        #pragma unroll
        for (int ks = 0; ks < 8; ks++) {
            const int kc = ks * 8;
            unsigned af[4];
            af[0] = __float_as_uint(Ps[r0][kc + c]);
            af[1] = __float_as_uint(Ps[r0 + 8][kc + c]);
            af[2] = __float_as_uint(Ps[r0][kc + c + 4]);
            af[3] = __float_as_uint(Ps[r0 + 8][kc + c + 4]);
            #pragma unroll
            for (int nt = 0; nt < 8; nt++) {
                unsigned bf[2];
                bf[0] = __float_as_uint(Vs[kc + c][nt * 8 + g]);
                bf[1] = __float_as_uint(Vs[kc + c + 4][nt * 8 + g]);
                mma_tf32(oacc[nt], af, bf);
            }
        }
    }

    // normalize + write concat layout [B*T, E]
    const float inv0 = 1.0f / l0, inv1 = 1.0f / l1;
    const size_t row0 = (size_t)(b * TSEQ + qbase + r0) * EMB + h * 64;
    const size_t row1 = row0 + (size_t)8 * EMB;
    #pragma unroll
    for (int nt = 0; nt < 8; nt++) {
        const int cc = nt * 8 + 2 * c;
        *(float2*)&out[row0 + cc] = make_float2(oacc[nt][0] * inv0, oacc[nt][1] * inv0);
        *(float2*)&out[row1 + cc] = make_float2(oacc[nt][2] * inv1, oacc[nt][3] * inv1);
    }
}

// ---------------------------------------------------------------------------
static float* sym_addr(const void* symbol)
{
    void* p = nullptr;
    cudaGetSymbolAddress(&p, symbol);
    return (float*)p;
}

extern "C" void kernel_launch(void* const* d_in, const int* in_sizes, int n_in,
                              void* d_out, int out_size)
{
    (void)in_sizes; (void)n_in; (void)out_size;
    const float* x      = (const float*)d_in[0];
    const float* Wq     = (const float*)d_in[1];
    const float* bq     = (const float*)d_in[2];
    const float* Wk     = (const float*)d_in[3];
    const float* bk     = (const float*)d_in[4];
    const float* Wv     = (const float*)d_in[5];
    const float* bv     = (const float*)d_in[6];
    const float* Wo     = (const float*)d_in[7];
    const float* bo     = (const float*)d_in[8];
    const float* W1     = (const float*)d_in[9];
    const float* b1     = (const float*)d_in[10];
    const float* W2     = (const float*)d_in[11];
    const float* b2     = (const float*)d_in[12];
    const float* gamma1 = (const float*)d_in[13];
    const float* beta1  = (const float*)d_in[14];
    const float* gamma2 = (const float*)d_in[15];
    const float* beta2  = (const float*)d_in[16];
    float* out = (float*)d_out;

    float* xn  = sym_addr(g_xn);
    float* qb  = sym_addr(g_q);
    float* kb2 = sym_addr(g_k);
    float* vb2 = sym_addr(g_v);
    float* att = sym_addr(g_att);
    float* x1  = sym_addr(g_x1);
    float* hb  = sym_addr(g_h);

    // 1. LN1
    ln_kernel<<<MROWS, 256>>>(x, gamma1, beta1, xn);
    // 2. QKV projections
    mma_gemm<2, true><<<dim3(EMB / 128, MROWS / 128), 256>>>(
        xn, Wq, bq, nullptr, qb, MROWS, EMB, EMB);
    mma_gemm<2, true><<<dim3(EMB / 128, MROWS / 128), 256>>>(
        xn, Wk, bk, nullptr, kb2, MROWS, EMB, EMB);
    mma_gemm<2, true><<<dim3(EMB / 128, MROWS / 128), 256>>>(
        xn, Wv, bv, nullptr, vb2, MROWS, EMB, EMB);
    // 3. causal attention (tensor core) -> [B*T, E]
    attn_mma<<<dim3(TSEQ / 64, BATCH * HEADS), 128>>>(qb, kb2, vb2, att);
    // 4. output projection + residual
    mma_gemm<1, false><<<dim3(EMB / 128, MROWS / 128), 256>>>(
        att, Wo, bo, x, x1, MROWS, EMB, EMB);
    // 5. LN2
    ln_kernel<<<MROWS, 256>>>(x1, gamma2, beta2, xn);
    // 6. FFN1
    mma_gemm<0, false><<<dim3(DFF / 128, MROWS / 128), 256>>>(
        xn, W1, b1, nullptr, hb, MROWS, DFF, EMB);
    // 7. FFN2 + residual -> out
    mma_gemm<1, false><<<dim3(EMB / 128, MROWS / 128), 256>>>(
        hb, W2, b2, x1, out, MROWS, EMB, DFF);
}

// round 8
// speedup vs baseline: 5.2775x; 1.0759x over previous
#include <cuda_runtime.h>
#include <math.h>
#include <stdint.h>

#define BATCH 2
#define TSEQ  2048
#define EMB   1024
#define HEADS 16
#define DHEAD 64
#define DFF   4096
#define MROWS 4096   // BATCH*TSEQ

// -------- scratch --------
__device__ float g_xn [(size_t)MROWS * EMB];
__device__ float g_q  [(size_t)BATCH * HEADS * TSEQ * DHEAD];
__device__ float g_k  [(size_t)BATCH * HEADS * TSEQ * DHEAD];
__device__ float g_v  [(size_t)BATCH * HEADS * TSEQ * DHEAD];
__device__ float g_att[(size_t)MROWS * EMB];
__device__ float g_x1 [(size_t)MROWS * EMB];
__device__ float g_h  [(size_t)MROWS * DFF];
// transposed (K-major, tf32-rounded) weights
__device__ float g_wt  [(size_t)3 * EMB * EMB];   // [3072][1024] fused QKV
__device__ float g_bqkv[3 * EMB];
__device__ float g_wot [(size_t)EMB * EMB];       // [1024][1024]
__device__ float g_w1t [(size_t)DFF * EMB];       // [4096][1024]
__device__ float g_w2t [(size_t)EMB * DFF];       // [1024][4096]

// ---------------------------------------------------------------------------
// helpers
// ---------------------------------------------------------------------------
__device__ __forceinline__ unsigned f2tf32(float f) {
    unsigned u;
    asm("cvt.rna.tf32.f32 %0, %1;" : "=r"(u) : "f"(f));
    return u;
}
__device__ __forceinline__ void mma_tf32(float* d, const unsigned* a, const unsigned* b) {
    asm volatile(
        "mma.sync.aligned.m16n8k8.row.col.f32.tf32.tf32.f32 "
        "{%0,%1,%2,%3},{%4,%5,%6,%7},{%8,%9},{%0,%1,%2,%3};\n"
        : "+f"(d[0]), "+f"(d[1]), "+f"(d[2]), "+f"(d[3])
        : "r"(a[0]), "r"(a[1]), "r"(a[2]), "r"(a[3]), "r"(b[0]), "r"(b[1]));
}
__device__ __forceinline__ uint32_t s2u(const void* p) {
    uint32_t a;
    asm("{ .reg .u64 t; cvta.to.shared.u64 t, %1; cvt.u32.u64 %0, t; }"
        : "=r"(a) : "l"(p));
    return a;
}
__device__ __forceinline__ void cpa16(uint32_t dst, const void* src) {
    asm volatile("cp.async.cg.shared.global [%0], [%1], 16;"
                 :: "r"(dst), "l"(src) : "memory");
}
#define CP_COMMIT() asm volatile("cp.async.commit_group;" ::: "memory")
#define CP_WAIT1()  asm volatile("cp.async.wait_group 1;" ::: "memory")
#define CP_WAIT0()  asm volatile("cp.async.wait_group 0;" ::: "memory")

// swizzled float index inside a [rows][32-float] tile (128B rows, 16B chunks)
__device__ __forceinline__ int sws(int row, int w) {
    return row * 32 + ((((w >> 2) ^ (row & 7)) << 2) | (w & 3));
}

// ---------------------------------------------------------------------------
// LayerNorm — writes tf32-rounded output (consumed only as GEMM A operand)
// ---------------------------------------------------------------------------
__global__ __launch_bounds__(256) void ln_kernel(
    const float* __restrict__ in, const float* __restrict__ gamma,
    const float* __restrict__ beta, float* __restrict__ out)
{
    __shared__ float red[16];
    const int tid = threadIdx.x;
    const float* xr = in + (size_t)blockIdx.x * EMB;
    float4 xv = *(const float4*)(xr + tid * 4);

    float s = xv.x + xv.y + xv.z + xv.w;
    #pragma unroll
    for (int o = 16; o > 0; o >>= 1) s += __shfl_xor_sync(0xffffffffu, s, o);
    if ((tid & 31) == 0) red[tid >> 5] = s;
    __syncthreads();
    float tot = 0.f;
    #pragma unroll
    for (int i = 0; i < 8; i++) tot += red[i];
    const float mu = tot * (1.0f / EMB);

    const float dx = xv.x - mu, dy = xv.y - mu, dz = xv.z - mu, dw = xv.w - mu;
    float ss = dx*dx + dy*dy + dz*dz + dw*dw;
    #pragma unroll
    for (int o = 16; o > 0; o >>= 1) ss += __shfl_xor_sync(0xffffffffu, ss, o);
    if ((tid & 31) == 0) red[8 + (tid >> 5)] = ss;
    __syncthreads();
    float vtot = 0.f;
    #pragma unroll
    for (int i = 0; i < 8; i++) vtot += red[8 + i];
    const float inv = rsqrtf(vtot * (1.0f / EMB) + 1e-5f);

    float4 gv = *(const float4*)(gamma + tid * 4);
    float4 bv = *(const float4*)(beta  + tid * 4);
    float4 r;
    r.x = __uint_as_float(f2tf32(dx * inv * gv.x + bv.x));
    r.y = __uint_as_float(f2tf32(dy * inv * gv.y + bv.y));
    r.z = __uint_as_float(f2tf32(dz * inv * gv.z + bv.z));
    r.w = __uint_as_float(f2tf32(dw * inv * gv.w + bv.w));
    *(float4*)(out + (size_t)blockIdx.x * EMB + tid * 4) = r;
}

// ---------------------------------------------------------------------------
// Weight transposes -> K-major [N,K], tf32-pre-rounded
// ---------------------------------------------------------------------------
__global__ void trans_w(const float* __restrict__ in, float* __restrict__ out,
                        int K, int N)
{   // in [K,N] -> out [N,K]; block (32,8), grid (N/32, K/32)
    __shared__ float t[32][33];
    const int n0 = blockIdx.x * 32, k0 = blockIdx.y * 32;
    const int tx = threadIdx.x, ty = threadIdx.y;
    #pragma unroll
    for (int i = 0; i < 32; i += 8)
        t[ty + i][tx] = in[(size_t)(k0 + ty + i) * N + n0 + tx];
    __syncthreads();
    #pragma unroll
    for (int i = 0; i < 32; i += 8)
        out[(size_t)(n0 + ty + i) * K + k0 + tx] =
            __uint_as_float(f2tf32(t[tx][ty + i]));
}

__global__ void trans_qkv(const float* __restrict__ Wq, const float* __restrict__ Wk,
                          const float* __restrict__ Wv, float* __restrict__ out)
{   // W[z][h][E][64] -> out[(z*16+h)*64 + d][e]; grid (2, 32, 48), block (32,8)
    const int zh = blockIdx.z;
    const int z = zh >> 4;
    const float* W = (z == 0 ? Wq : z == 1 ? Wk : Wv) + (size_t)(zh & 15) * EMB * 64;
    __shared__ float t[32][33];
    const int d0 = blockIdx.x * 32, k0 = blockIdx.y * 32;
    const int tx = threadIdx.x, ty = threadIdx.y;
    #pragma unroll
    for (int i = 0; i < 32; i += 8)
        t[ty + i][tx] = W[(size_t)(k0 + ty + i) * 64 + d0 + tx];
    __syncthreads();
    float* o = out + (size_t)zh * 64 * EMB;
    #pragma unroll
    for (int i = 0; i < 32; i += 8)
        o[(size_t)(d0 + ty + i) * EMB + k0 + tx] =
            __uint_as_float(f2tf32(t[tx][ty + i]));
}

__global__ void pack_bias(const float* __restrict__ bq, const float* __restrict__ bk,
                          const float* __restrict__ bv, float* __restrict__ o)
{
    const int n = blockIdx.x * 256 + threadIdx.x;
    const float* b = n < 1024 ? bq : n < 2048 ? bk : bv;
    o[n] = b[n & 1023];
}

// ---------------------------------------------------------------------------
// TF32 mma.sync GEMM, cp.async pipeline.
// CTA tile 128x128, k-chunk 32, 2-stage smem double buffer (64KB).
// A [M,K] and Bt [N,K] both K-major, tf32-pre-rounded by producers.
// 8 warps as 2(M) x 4(N); warp tile 64x32; m16n8k8.
// MODE 0: relu(acc+bias), tf32-rounded  (FFN1)
// MODE 1: resid+acc+bias                (Wo, FFN2)
// MODE 2: fused QKV scatter to [B,H,T,DH] x3
// ---------------------------------------------------------------------------
#define STAGE_BYTES 32768      // A 16KB + B 16KB
#define SMEM_DYN    (2 * STAGE_BYTES)

template<int MODE>
__global__ __launch_bounds__(256) void tc_gemm(
    const float* __restrict__ A, const float* __restrict__ Bt,
    const float* __restrict__ bias, const float* __restrict__ resid,
    float* __restrict__ C0, float* __restrict__ C1, float* __restrict__ C2,
    int N, int K)
{
    extern __shared__ char smem[];
    const uint32_t sb = s2u(smem);
    const int tid = threadIdx.x;
    const int lane = tid & 31, warp = tid >> 5;
    const int warpM = warp & 1, warpN = warp >> 1;
    const int g = lane >> 2, c = lane & 3;
    const int bm = blockIdx.y * 128, bn = blockIdx.x * 128;

    float acc[64];
    #pragma unroll
    for (int i = 0; i < 64; i++) acc[i] = 0.f;

    // cp.async slots: 1024 16B-chunks per 16KB tile; 4 per thread per tile
    int rowA[4], chA[4];
    #pragma unroll
    for (int j = 0; j < 4; j++) {
        const int idx = j * 256 + tid;
        rowA[j] = idx >> 3;
        chA[j]  = idx & 7;
    }

    auto issue = [&](int t, int buf) {
        const int k0 = t << 5;
        const uint32_t base = sb + buf * STAGE_BYTES;
        #pragma unroll
        for (int j = 0; j < 4; j++) {
            const int row = rowA[j], ch = chA[j];
            const uint32_t off = row * 128 + ((ch ^ (row & 7)) << 4);
            cpa16(base + off,
                  A + (size_t)(bm + row) * K + k0 + ch * 4);
            cpa16(base + 16384 + off,
                  Bt + (size_t)(bn + row) * K + k0 + ch * 4);
        }
        CP_COMMIT();
    };

    const int nk = K >> 5;
    issue(0, 0);
    if (nk > 1) issue(1, 1);

    for (int t = 0; t < nk; ++t) {
        const int buf = t & 1;
        if (t + 1 < nk) { CP_WAIT1(); } else { CP_WAIT0(); }
        __syncthreads();

        const float* sA = (const float*)(smem + buf * STAGE_BYTES);
        const float* sB = (const float*)(smem + buf * STAGE_BYTES + 16384);

        #pragma unroll
        for (int ks = 0; ks < 4; ++ks) {
            const int w0 = ks * 8 + c;
            unsigned af[4][4], bf[4][2];
            #pragma unroll
            for (int mt = 0; mt < 4; mt++) {
                const int r = warpM * 64 + mt * 16 + g;
                af[mt][0] = __float_as_uint(sA[sws(r,     w0)]);
                af[mt][1] = __float_as_uint(sA[sws(r + 8, w0)]);
                af[mt][2] = __float_as_uint(sA[sws(r,     w0 + 4)]);
                af[mt][3] = __float_as_uint(sA[sws(r + 8, w0 + 4)]);
            }
            #pragma unroll
            for (int nt = 0; nt < 4; nt++) {
                const int col = warpN * 32 + nt * 8 + g;
                bf[nt][0] = __float_as_uint(sB[sws(col, w0)]);
                bf[nt][1] = __float_as_uint(sB[sws(col, w0 + 4)]);
            }
            #pragma unroll
            for (int mt = 0; mt < 4; mt++)
                #pragma unroll
                for (int nt = 0; nt < 4; nt++)
                    mma_tf32(&acc[(mt * 4 + nt) * 4], af[mt], bf[nt]);
        }

        __syncthreads();
        if (t + 2 < nk) issue(t + 2, buf);
    }

    // ---- epilogue ----
    #pragma unroll
    for (int mt = 0; mt < 4; mt++) {
        const int r0 = bm + warpM * 64 + mt * 16 + g;
        const int r1 = r0 + 8;
        #pragma unroll
        for (int nt = 0; nt < 4; nt++) {
            const int nn = bn + warpN * 32 + nt * 8 + 2 * c;
            const float* a = &acc[(mt * 4 + nt) * 4];
            float2 bb = *(const float2*)&bias[nn];
            float v00 = a[0] + bb.x, v01 = a[1] + bb.y;
            float v10 = a[2] + bb.x, v11 = a[3] + bb.y;
            if (MODE == 0) {
                v00 = __uint_as_float(f2tf32(fmaxf(v00, 0.f)));
                v01 = __uint_as_float(f2tf32(fmaxf(v01, 0.f)));
                v10 = __uint_as_float(f2tf32(fmaxf(v10, 0.f)));
                v11 = __uint_as_float(f2tf32(fmaxf(v11, 0.f)));
                *(float2*)&C0[(size_t)r0 * N + nn] = make_float2(v00, v01);
                *(float2*)&C0[(size_t)r1 * N + nn] = make_float2(v10, v11);
            } else if (MODE == 1) {
                float2 rr0 = *(const float2*)&resid[(size_t)r0 * N + nn];
                float2 rr1 = *(const float2*)&resid[(size_t)r1 * N + nn];
                *(float2*)&C0[(size_t)r0 * N + nn] = make_float2(v00 + rr0.x, v01 + rr0.y);
                *(float2*)&C0[(size_t)r1 * N + nn] = make_float2(v10 + rr1.x, v11 + rr1.y);
            } else {
                const int z = nn >> 10;
                float* O = (z == 0) ? C0 : (z == 1) ? C1 : C2;
                const int h = (nn & 1023) >> 6, d = nn & 63;
                const int b0 = r0 >> 11, t0i = r0 & 2047;
                const int b1 = r1 >> 11, t1i = r1 & 2047;
                *(float2*)&O[((((size_t)(b0 * HEADS + h)) * TSEQ + t0i) << 6) + d] =
                    make_float2(v00, v01);
                *(float2*)&O[((((size_t)(b1 * HEADS + h)) * TSEQ + t1i) << 6) + d] =
                    make_float2(v10, v11);
            }
        }
    }
}

// ---------------------------------------------------------------------------
// TF32 tensor-core causal flash attention (R3); output tf32-rounded.
// ---------------------------------------------------------------------------
__global__ __launch_bounds__(128) void attn_mma(
    const float* __restrict__ q, const float* __restrict__ k,
    const float* __restrict__ v, float* __restrict__ out)
{
    __shared__ float Ks[64][68];
    __shared__ float Vs[64][68];

    const int bh = blockIdx.y;
    const int b = bh >> 4, h = bh & 15;
    const int qt = blockIdx.x;
    const int qbase = qt * 64;
    const float* Q  = q + (size_t)bh * TSEQ * DHEAD;
    const float* Kp = k + (size_t)bh * TSEQ * DHEAD;
    const float* Vp = v + (size_t)bh * TSEQ * DHEAD;

    const int tid = threadIdx.x;
    const int lane = tid & 31, w = tid >> 5;
    const int g = lane >> 2, c = lane & 3;
    const int r0 = w * 16 + g;

    unsigned qf[8][4];
    #pragma unroll
    for (int ks = 0; ks < 8; ks++) {
        const int kc = ks * 8;
        qf[ks][0] = f2tf32(0.125f * Q[(size_t)(qbase + r0)     * 64 + kc + c]);
        qf[ks][1] = f2tf32(0.125f * Q[(size_t)(qbase + r0 + 8) * 64 + kc + c]);
        qf[ks][2] = f2tf32(0.125f * Q[(size_t)(qbase + r0)     * 64 + kc + c + 4]);
        qf[ks][3] = f2tf32(0.125f * Q[(size_t)(qbase + r0 + 8) * 64 + kc + c + 4]);
    }

    float oacc[8][4];
    #pragma unroll
    for (int i = 0; i < 8; i++)
        #pragma unroll
        for (int j = 0; j < 4; j++) oacc[i][j] = 0.f;
    float m0 = -1e30f, m1 = -1e30f, l0 = 0.f, l1 = 0.f;

    for (int t = 0; t <= qt; t++) {
        const int kb = t * 64;
        __syncthreads();
        #pragma unroll
        for (int i = 0; i < 8; i++) {
            const int idx = i * 128 + tid;
            const int row = idx >> 4, col = (idx & 15) << 2;
            float4 kv = *(const float4*)&Kp[(size_t)(kb + row) * 64 + col];
            float4 vv = *(const float4*)&Vp[(size_t)(kb + row) * 64 + col];
            float4 ko, vo;
            ko.x = __uint_as_float(f2tf32(kv.x)); ko.y = __uint_as_float(f2tf32(kv.y));
            ko.z = __uint_as_float(f2tf32(kv.z)); ko.w = __uint_as_float(f2tf32(kv.w));
            vo.x = __uint_as_float(f2tf32(vv.x)); vo.y = __uint_as_float(f2tf32(vv.y));
            vo.z = __uint_as_float(f2tf32(vv.z)); vo.w = __uint_as_float(f2tf32(vv.w));
            *(float4*)&Ks[row][col] = ko;
            *(float4*)&Vs[row][col] = vo;
        }
        __syncthreads();

        float sacc[8][4];
        #pragma unroll
        for (int i = 0; i < 8; i++)
            #pragma unroll
            for (int j = 0; j < 4; j++) sacc[i][j] = 0.f;
        #pragma unroll
        for (int ks = 0; ks < 8; ks++) {
            const int kc = ks * 8;
            #pragma unroll
            for (int nt = 0; nt < 8; nt++) {
                unsigned bf[2];
                bf[0] = __float_as_uint(Ks[nt * 8 + g][kc + c]);
                bf[1] = __float_as_uint(Ks[nt * 8 + g][kc + c + 4]);
                mma_tf32(sacc[nt], qf[ks], bf);
            }
        }
        __syncthreads();

        if (t == qt) {
            #pragma unroll
            for (int nt = 0; nt < 8; nt++) {
                const int c0 = nt * 8 + 2 * c, c1 = c0 + 1;
                if (c0 > r0)     sacc[nt][0] = -1e30f;
                if (c1 > r0)     sacc[nt][1] = -1e30f;
                if (c0 > r0 + 8) sacc[nt][2] = -1e30f;
                if (c1 > r0 + 8) sacc[nt][3] = -1e30f;
            }
        }

        float mx0 = m0, mx1 = m1;
        #pragma unroll
        for (int nt = 0; nt < 8; nt++) {
            mx0 = fmaxf(mx0, fmaxf(sacc[nt][0], sacc[nt][1]));
            mx1 = fmaxf(mx1, fmaxf(sacc[nt][2], sacc[nt][3]));
        }
        #pragma unroll
        for (int o = 1; o <= 2; o <<= 1) {
            mx0 = fmaxf(mx0, __shfl_xor_sync(0xffffffffu, mx0, o));
            mx1 = fmaxf(mx1, __shfl_xor_sync(0xffffffffu, mx1, o));
        }
        const float rs0 = __expf(m0 - mx0), rs1 = __expf(m1 - mx1);
        m0 = mx0; m1 = mx1;

        float (*Ps)[68] = Ks;
        float sum0 = 0.f, sum1 = 0.f;
        #pragma unroll
        for (int nt = 0; nt < 8; nt++) {
            const int cc = nt * 8 + 2 * c;
            float p00 = __expf(sacc[nt][0] - mx0);
            float p01 = __expf(sacc[nt][1] - mx0);
            float p10 = __expf(sacc[nt][2] - mx1);
            float p11 = __expf(sacc[nt][3] - mx1);
            sum0 += p00 + p01;
            sum1 += p10 + p11;
            *(float2*)&Ps[r0][cc] = make_float2(
                __uint_as_float(f2tf32(p00)), __uint_as_float(f2tf32(p01)));
            *(float2*)&Ps[r0 + 8][cc] = make_float2(
                __uint_as_float(f2tf32(p10)), __uint_as_float(f2tf32(p11)));
        }
        #pragma unroll
        for (int o = 1; o <= 2; o <<= 1) {
            sum0 += __shfl_xor_sync(0xffffffffu, sum0, o);
            sum1 += __shfl_xor_sync(0xffffffffu, sum1, o);
        }
        l0 = l0 * rs0 + sum0;
        l1 = l1 * rs1 + sum1;
        #pragma unroll
        for (int nt = 0; nt < 8; nt++) {
            oacc[nt][0] *= rs0; oacc[nt][1] *= rs0;
            oacc[nt][2] *= rs1; oacc[nt][3] *= rs1;
        }
        __syncwarp();

        #pragma unroll
        for (int ks = 0; ks < 8; ks++) {
            const int kc = ks * 8;
            unsigned af[4];
            af[0] = __float_as_uint(Ps[r0][kc + c]);
            af[1] = __float_as_uint(Ps[r0 + 8][kc + c]);
            af[2] = __float_as_uint(Ps[r0][kc + c + 4]);
            af[3] = __float_as_uint(Ps[r0 + 8][kc + c + 4]);
            #pragma unroll
            for (int nt = 0; nt < 8; nt++) {
                unsigned bf[2];
                bf[0] = __float_as_uint(Vs[kc + c][nt * 8 + g]);
                bf[1] = __float_as_uint(Vs[kc + c + 4][nt * 8 + g]);
                mma_tf32(oacc[nt], af, bf);
            }
        }
    }

    const float inv0 = 1.0f / l0, inv1 = 1.0f / l1;
    const size_t row0 = (size_t)(b * TSEQ + qbase + r0) * EMB + h * 64;
    const size_t row1 = row0 + (size_t)8 * EMB;
    #pragma unroll
    for (int nt = 0; nt < 8; nt++) {
        const int cc = nt * 8 + 2 * c;
        *(float2*)&out[row0 + cc] = make_float2(
            __uint_as_float(f2tf32(oacc[nt][0] * inv0)),
            __uint_as_float(f2tf32(oacc[nt][1] * inv0)));
        *(float2*)&out[row1 + cc] = make_float2(
            __uint_as_float(f2tf32(oacc[nt][2] * inv1)),
            __uint_as_float(f2tf32(oacc[nt][3] * inv1)));
    }
}

// ---------------------------------------------------------------------------
static float* sym_addr(const void* symbol)
{
    void* p = nullptr;
    cudaGetSymbolAddress(&p, symbol);
    return (float*)p;
}

extern "C" void kernel_launch(void* const* d_in, const int* in_sizes, int n_in,
                              void* d_out, int out_size)
{
    (void)in_sizes; (void)n_in; (void)out_size;
    const float* x      = (const float*)d_in[0];
    const float* Wq     = (const float*)d_in[1];
    const float* bq     = (const float*)d_in[2];
    const float* Wk     = (const float*)d_in[3];
    const float* bk     = (const float*)d_in[4];
    const float* Wv     = (const float*)d_in[5];
    const float* bv     = (const float*)d_in[6];
    const float* Wo     = (const float*)d_in[7];
    const float* bo     = (const float*)d_in[8];
    const float* W1     = (const float*)d_in[9];
    const float* b1     = (const float*)d_in[10];
    const float* W2     = (const float*)d_in[11];
    const float* b2     = (const float*)d_in[12];
    const float* gamma1 = (const float*)d_in[13];
    const float* beta1  = (const float*)d_in[14];
    const float* gamma2 = (const float*)d_in[15];
    const float* beta2  = (const float*)d_in[16];
    float* out = (float*)d_out;

    float* xn   = sym_addr(g_xn);
    float* qb   = sym_addr(g_q);
    float* kb2  = sym_addr(g_k);
    float* vb2  = sym_addr(g_v);
    float* att  = sym_addr(g_att);
    float* x1   = sym_addr(g_x1);
    float* hb   = sym_addr(g_h);
    float* wt   = sym_addr(g_wt);
    float* bqkv = sym_addr(g_bqkv);
    float* wot  = sym_addr(g_wot);
    float* w1t  = sym_addr(g_w1t);
    float* w2t  = sym_addr(g_w2t);

    cudaFuncSetAttribute(tc_gemm<0>, cudaFuncAttributeMaxDynamicSharedMemorySize, SMEM_DYN);
    cudaFuncSetAttribute(tc_gemm<1>, cudaFuncAttributeMaxDynamicSharedMemorySize, SMEM_DYN);
    cudaFuncSetAttribute(tc_gemm<2>, cudaFuncAttributeMaxDynamicSharedMemorySize, SMEM_DYN);

    // 0. weight transposes (+tf32 rounding) and bias pack
    trans_qkv<<<dim3(2, 32, 48), dim3(32, 8)>>>(Wq, Wk, Wv, wt);
    pack_bias<<<12, 256>>>(bq, bk, bv, bqkv);
    trans_w<<<dim3(32, 32),  dim3(32, 8)>>>(Wo, wot, EMB, EMB);
    trans_w<<<dim3(128, 32), dim3(32, 8)>>>(W1, w1t, EMB, DFF);
    trans_w<<<dim3(32, 128), dim3(32, 8)>>>(W2, w2t, DFF, EMB);

    // 1. LN1 (tf32-rounded output)
    ln_kernel<<<MROWS, 256>>>(x, gamma1, beta1, xn);
    // 2. fused QKV projection
    tc_gemm<2><<<dim3(24, 32), 256, SMEM_DYN>>>(
        xn, wt, bqkv, nullptr, qb, kb2, vb2, 3 * EMB, EMB);
    // 3. causal attention -> [B*T, E] (tf32-rounded)
    attn_mma<<<dim3(TSEQ / 64, BATCH * HEADS), 128>>>(qb, kb2, vb2, att);
    // 4. output projection + residual
    tc_gemm<1><<<dim3(8, 32), 256, SMEM_DYN>>>(
        att, wot, bo, x, x1, nullptr, nullptr, EMB, EMB);
    // 5. LN2 (tf32-rounded output)
    ln_kernel<<<MROWS, 256>>>(x1, gamma2, beta2, xn);
    // 6. FFN1 (relu, tf32-rounded output)
    tc_gemm<0><<<dim3(32, 32), 256, SMEM_DYN>>>(
        xn, w1t, b1, nullptr, hb, nullptr, nullptr, DFF, EMB);
    // 7. FFN2 + residual -> out
    tc_gemm<1><<<dim3(8, 32), 256, SMEM_DYN>>>(
        hb, w2t, b2, x1, out, nullptr, nullptr, EMB, DFF);
}

// round 12
// speedup vs baseline: 6.2992x; 1.1936x over previous
#include <cuda_runtime.h>
#include <math.h>
#include <stdint.h>

#define BATCH 2
#define TSEQ  2048
#define EMB   1024
#define HEADS 16
#define DHEAD 64
#define DFF   4096
#define MROWS 4096   // BATCH*TSEQ

// -------- scratch --------
__device__ float g_xn [(size_t)MROWS * EMB];
__device__ float g_q  [(size_t)BATCH * HEADS * TSEQ * DHEAD];
__device__ float g_k  [(size_t)BATCH * HEADS * TSEQ * DHEAD];
__device__ float g_v  [(size_t)BATCH * HEADS * TSEQ * DHEAD];
__device__ float g_att[(size_t)MROWS * EMB];
__device__ float g_x1 [(size_t)MROWS * EMB];
__device__ float g_h  [(size_t)MROWS * DFF];
// transposed (K-major, tf32-rounded) weights
__device__ float g_wt  [(size_t)3 * EMB * EMB];   // [3072][1024] fused QKV
__device__ float g_bqkv[3 * EMB];
__device__ float g_wot [(size_t)EMB * EMB];       // [1024][1024]
__device__ float g_w1t [(size_t)DFF * EMB];       // [4096][1024]
__device__ float g_w2t [(size_t)EMB * DFF];       // [1024][4096]

// ---------------------------------------------------------------------------
// helpers
// ---------------------------------------------------------------------------
__device__ __forceinline__ unsigned f2tf32(float f) {
    unsigned u;
    asm("cvt.rna.tf32.f32 %0, %1;" : "=r"(u) : "f"(f));
    return u;
}
__device__ __forceinline__ void mma_tf32(float* d, const unsigned* a, const unsigned* b) {
    asm volatile(
        "mma.sync.aligned.m16n8k8.row.col.f32.tf32.tf32.f32 "
        "{%0,%1,%2,%3},{%4,%5,%6,%7},{%8,%9},{%0,%1,%2,%3};\n"
        : "+f"(d[0]), "+f"(d[1]), "+f"(d[2]), "+f"(d[3])
        : "r"(a[0]), "r"(a[1]), "r"(a[2]), "r"(a[3]), "r"(b[0]), "r"(b[1]));
}
__device__ __forceinline__ void ldsm4(unsigned* d, uint32_t a) {
    asm volatile("ldmatrix.sync.aligned.m8n8.x4.shared.b16 {%0,%1,%2,%3}, [%4];"
                 : "=r"(d[0]), "=r"(d[1]), "=r"(d[2]), "=r"(d[3]) : "r"(a));
}
__device__ __forceinline__ uint32_t s2u(const void* p) {
    uint32_t a;
    asm("{ .reg .u64 t; cvta.to.shared.u64 t, %1; cvt.u32.u64 %0, t; }"
        : "=r"(a) : "l"(p));
    return a;
}
__device__ __forceinline__ void cpa16(uint32_t dst, const void* src) {
    asm volatile("cp.async.cg.shared.global [%0], [%1], 16;"
                 :: "r"(dst), "l"(src) : "memory");
}
#define CP_COMMIT() asm volatile("cp.async.commit_group;" ::: "memory")
#define CP_WAIT1()  asm volatile("cp.async.wait_group 1;" ::: "memory")
#define CP_WAIT0()  asm volatile("cp.async.wait_group 0;" ::: "memory")

// ---------------------------------------------------------------------------
// LayerNorm — writes tf32-rounded output (consumed only as GEMM A operand)
// ---------------------------------------------------------------------------
__global__ __launch_bounds__(256) void ln_kernel(
    const float* __restrict__ in, const float* __restrict__ gamma,
    const float* __restrict__ beta, float* __restrict__ out)
{
    __shared__ float red[16];
    const int tid = threadIdx.x;
    const float* xr = in + (size_t)blockIdx.x * EMB;
    float4 xv = *(const float4*)(xr + tid * 4);

    float s = xv.x + xv.y + xv.z + xv.w;
    #pragma unroll
    for (int o = 16; o > 0; o >>= 1) s += __shfl_xor_sync(0xffffffffu, s, o);
    if ((tid & 31) == 0) red[tid >> 5] = s;
    __syncthreads();
    float tot = 0.f;
    #pragma unroll
    for (int i = 0; i < 8; i++) tot += red[i];
    const float mu = tot * (1.0f / EMB);

    const float dx = xv.x - mu, dy = xv.y - mu, dz = xv.z - mu, dw = xv.w - mu;
    float ss = dx*dx + dy*dy + dz*dz + dw*dw;
    #pragma unroll
    for (int o = 16; o > 0; o >>= 1) ss += __shfl_xor_sync(0xffffffffu, ss, o);
    if ((tid & 31) == 0) red[8 + (tid >> 5)] = ss;
    __syncthreads();
    float vtot = 0.f;
    #pragma unroll
    for (int i = 0; i < 8; i++) vtot += red[8 + i];
    const float inv = rsqrtf(vtot * (1.0f / EMB) + 1e-5f);

    float4 gv = *(const float4*)(gamma + tid * 4);
    float4 bv = *(const float4*)(beta  + tid * 4);
    float4 r;
    r.x = __uint_as_float(f2tf32(dx * inv * gv.x + bv.x));
    r.y = __uint_as_float(f2tf32(dy * inv * gv.y + bv.y));
    r.z = __uint_as_float(f2tf32(dz * inv * gv.z + bv.z));
    r.w = __uint_as_float(f2tf32(dw * inv * gv.w + bv.w));
    *(float4*)(out + (size_t)blockIdx.x * EMB + tid * 4) = r;
}

// ---------------------------------------------------------------------------
// Weight transposes -> K-major [N,K], tf32-pre-rounded
// ---------------------------------------------------------------------------
__global__ void trans_w(const float* __restrict__ in, float* __restrict__ out,
                        int K, int N)
{   // in [K,N] -> out [N,K]; block (32,8), grid (N/32, K/32)
    __shared__ float t[32][33];
    const int n0 = blockIdx.x * 32, k0 = blockIdx.y * 32;
    const int tx = threadIdx.x, ty = threadIdx.y;
    #pragma unroll
    for (int i = 0; i < 32; i += 8)
        t[ty + i][tx] = in[(size_t)(k0 + ty + i) * N + n0 + tx];
    __syncthreads();
    #pragma unroll
    for (int i = 0; i < 32; i += 8)
        out[(size_t)(n0 + ty + i) * K + k0 + tx] =
            __uint_as_float(f2tf32(t[tx][ty + i]));
}

__global__ void trans_qkv(const float* __restrict__ Wq, const float* __restrict__ Wk,
                          const float* __restrict__ Wv, float* __restrict__ out)
{   // W[z][h][E][64] -> out[(z*16+h)*64 + d][e]; grid (2, 32, 48), block (32,8)
    const int zh = blockIdx.z;
    const int z = zh >> 4;
    const float* W = (z == 0 ? Wq : z == 1 ? Wk : Wv) + (size_t)(zh & 15) * EMB * 64;
    __shared__ float t[32][33];
    const int d0 = blockIdx.x * 32, k0 = blockIdx.y * 32;
    const int tx = threadIdx.x, ty = threadIdx.y;
    #pragma unroll
    for (int i = 0; i < 32; i += 8)
        t[ty + i][tx] = W[(size_t)(k0 + ty + i) * 64 + d0 + tx];
    __syncthreads();
    float* o = out + (size_t)zh * 64 * EMB;
    #pragma unroll
    for (int i = 0; i < 32; i += 8)
        o[(size_t)(d0 + ty + i) * EMB + k0 + tx] =
            __uint_as_float(f2tf32(t[tx][ty + i]));
}

__global__ void pack_bias(const float* __restrict__ bq, const float* __restrict__ bk,
                          const float* __restrict__ bv, float* __restrict__ o)
{
    const int n = blockIdx.x * 256 + threadIdx.x;
    const float* b = n < 1024 ? bq : n < 2048 ? bk : bv;
    o[n] = b[n & 1023];
}

// ---------------------------------------------------------------------------
// TF32 mma.sync GEMM: cp.async 3-stage pipeline + ldmatrix fragment loads.
// CTA tile 128x128, k-chunk 32. A [M,K], Bt [N,K], both K-major tf32-rounded.
// 8 warps as 2(M) x 4(N); warp tile 64x32; m16n8k8.
// MODE 0: relu(acc+bias) tf32-rounded; MODE 1: resid+acc+bias; MODE 2: QKV scatter
// ---------------------------------------------------------------------------
#define STAGE_BYTES 32768      // A 16KB + B 16KB
#define NSTAGE 3
#define SMEM_DYN (NSTAGE * STAGE_BYTES)

template<int MODE>
__global__ __launch_bounds__(256) void tc_gemm(
    const float* __restrict__ A, const float* __restrict__ Bt,
    const float* __restrict__ bias, const float* __restrict__ resid,
    float* __restrict__ C0, float* __restrict__ C1, float* __restrict__ C2,
    int N, int K)
{
    extern __shared__ char smem[];
    const uint32_t sb = s2u(smem);
    const int tid = threadIdx.x;
    const int lane = tid & 31, warp = tid >> 5;
    const int warpM = warp & 1, warpN = warp >> 1;
    const int lane7 = lane & 7;
    const int bm = blockIdx.y * 128, bn = blockIdx.x * 128;

    float acc[64];
    #pragma unroll
    for (int i = 0; i < 64; i++) acc[i] = 0.f;

    // cp.async slots: 4 x 16B per thread per 16KB tile
    int rowA[4], chA[4];
    #pragma unroll
    for (int j = 0; j < 4; j++) {
        const int idx = j * 256 + tid;
        rowA[j] = idx >> 3;
        chA[j]  = idx & 7;
    }

    auto issue = [&](int t, int buf) {
        const int k0 = t << 5;
        const uint32_t base = sb + buf * STAGE_BYTES;
        #pragma unroll
        for (int j = 0; j < 4; j++) {
            const int row = rowA[j], ch = chA[j];
            const uint32_t off = row * 128 + ((ch ^ (row & 7)) << 4);
            cpa16(base + off,          A  + (size_t)(bm + row) * K + k0 + ch * 4);
            cpa16(base + 16384 + off,  Bt + (size_t)(bn + row) * K + k0 + ch * 4);
        }
        CP_COMMIT();
    };

    // ldmatrix per-lane invariants
    // A: matrices {rows r..r+7, r+8..r+15} x {chunk 2ks, 2ks+1}
    const int a_row_base = warpM * 64 + lane7 + ((lane >> 3) & 1) * 8;
    const int a_ch_sel   = lane >> 4;                 // 0/1 -> chunk +0/+1
    // B: matrices {colgrp j2, colgrp j2+1} x {chunk 2ks, 2ks+1}
    const int b_msel     = lane >> 3;                 // 0..3
    const int b_row_base = warpN * 32 + (b_msel >> 1) * 8 + lane7;
    const int b_ch_sel   = b_msel & 1;

    const int nk = K >> 5;
    issue(0, 0);
    issue(1, 1);

    for (int t = 0; t < nk; ++t) {
        const int buf = t % NSTAGE;
        if (t + 2 < nk) { CP_WAIT1(); } else { CP_WAIT0(); }
        __syncthreads();
        if (t + 2 < nk) issue(t + 2, (t + 2) % NSTAGE);

        const uint32_t ab = sb + buf * STAGE_BYTES;
        const uint32_t bb = ab + 16384;
        const uint32_t aBase = ab + a_row_base * 128;

        #pragma unroll
        for (int ks = 0; ks < 4; ++ks) {
            unsigned af[4][4], bf[4][2];
            #pragma unroll
            for (int mt = 0; mt < 4; mt++) {
                const uint32_t addr = aBase + mt * 2048 +
                    ((uint32_t)((2 * ks + a_ch_sel) ^ lane7) << 4);
                ldsm4(af[mt], addr);
            }
            #pragma unroll
            for (int j = 0; j < 2; j++) {
                unsigned d[4];
                const uint32_t addr = bb + (b_row_base + j * 16) * 128 +
                    ((uint32_t)((2 * ks + b_ch_sel) ^ lane7) << 4);
                ldsm4(d, addr);
                bf[2 * j][0]     = d[0]; bf[2 * j][1]     = d[1];
                bf[2 * j + 1][0] = d[2]; bf[2 * j + 1][1] = d[3];
            }
            #pragma unroll
            for (int mt = 0; mt < 4; mt++)
                #pragma unroll
                for (int nt = 0; nt < 4; nt++)
                    mma_tf32(&acc[(mt * 4 + nt) * 4], af[mt], bf[nt]);
        }
    }

    // ---- epilogue ----
    const int g = lane >> 2, c = lane & 3;
    #pragma unroll
    for (int mt = 0; mt < 4; mt++) {
        const int r0 = bm + warpM * 64 + mt * 16 + g;
        const int r1 = r0 + 8;
        #pragma unroll
        for (int nt = 0; nt < 4; nt++) {
            const int nn = bn + warpN * 32 + nt * 8 + 2 * c;
            const float* a = &acc[(mt * 4 + nt) * 4];
            float2 bb2 = *(const float2*)&bias[nn];
            float v00 = a[0] + bb2.x, v01 = a[1] + bb2.y;
            float v10 = a[2] + bb2.x, v11 = a[3] + bb2.y;
            if (MODE == 0) {
                v00 = __uint_as_float(f2tf32(fmaxf(v00, 0.f)));
                v01 = __uint_as_float(f2tf32(fmaxf(v01, 0.f)));
                v10 = __uint_as_float(f2tf32(fmaxf(v10, 0.f)));
                v11 = __uint_as_float(f2tf32(fmaxf(v11, 0.f)));
                *(float2*)&C0[(size_t)r0 * N + nn] = make_float2(v00, v01);
                *(float2*)&C0[(size_t)r1 * N + nn] = make_float2(v10, v11);
            } else if (MODE == 1) {
                float2 rr0 = *(const float2*)&resid[(size_t)r0 * N + nn];
                float2 rr1 = *(const float2*)&resid[(size_t)r1 * N + nn];
                *(float2*)&C0[(size_t)r0 * N + nn] = make_float2(v00 + rr0.x, v01 + rr0.y);
                *(float2*)&C0[(size_t)r1 * N + nn] = make_float2(v10 + rr1.x, v11 + rr1.y);
            } else {
                const int z = nn >> 10;
                float* O = (z == 0) ? C0 : (z == 1) ? C1 : C2;
                const int h = (nn & 1023) >> 6, d = nn & 63;
                const int b0 = r0 >> 11, t0i = r0 & 2047;
                const int b1 = r1 >> 11, t1i = r1 & 2047;
                *(float2*)&O[((((size_t)(b0 * HEADS + h)) * TSEQ + t0i) << 6) + d] =
                    make_float2(v00, v01);
                *(float2*)&O[((((size_t)(b1 * HEADS + h)) * TSEQ + t1i) << 6) + d] =
                    make_float2(v10, v11);
            }
        }
    }
}

// ---------------------------------------------------------------------------
// TF32 tensor-core causal flash attention (output tf32-rounded)
// ---------------------------------------------------------------------------
__global__ __launch_bounds__(128) void attn_mma(
    const float* __restrict__ q, const float* __restrict__ k,
    const float* __restrict__ v, float* __restrict__ out)
{
    __shared__ float Ks[64][68];
    __shared__ float Vs[64][68];

    const int bh = blockIdx.y;
    const int b = bh >> 4, h = bh & 15;
    const int qt = blockIdx.x;
    const int qbase = qt * 64;
    const float* Q  = q + (size_t)bh * TSEQ * DHEAD;
    const float* Kp = k + (size_t)bh * TSEQ * DHEAD;
    const float* Vp = v + (size_t)bh * TSEQ * DHEAD;

    const int tid = threadIdx.x;
    const int lane = tid & 31, w = tid >> 5;
    const int g = lane >> 2, c = lane & 3;
    const int r0 = w * 16 + g;

    unsigned qf[8][4];
    #pragma unroll
    for (int ks = 0; ks < 8; ks++) {
        const int kc = ks * 8;
        qf[ks][0] = f2tf32(0.125f * Q[(size_t)(qbase + r0)     * 64 + kc + c]);
        qf[ks][1] = f2tf32(0.125f * Q[(size_t)(qbase + r0 + 8) * 64 + kc + c]);
        qf[ks][2] = f2tf32(0.125f * Q[(size_t)(qbase + r0)     * 64 + kc + c + 4]);
        qf[ks][3] = f2tf32(0.125f * Q[(size_t)(qbase + r0 + 8) * 64 + kc + c + 4]);
    }

    float oacc[8][4];
    #pragma unroll
    for (int i = 0; i < 8; i++)
        #pragma unroll
        for (int j = 0; j < 4; j++) oacc[i][j] = 0.f;
    float m0 = -1e30f, m1 = -1e30f, l0 = 0.f, l1 = 0.f;

    for (int t = 0; t <= qt; t++) {
        const int kb = t * 64;
        __syncthreads();
        #pragma unroll
        for (int i = 0; i < 8; i++) {
            const int idx = i * 128 + tid;
            const int row = idx >> 4, col = (idx & 15) << 2;
            float4 kv = *(const float4*)&Kp[(size_t)(kb + row) * 64 + col];
            float4 vv = *(const float4*)&Vp[(size_t)(kb + row) * 64 + col];
            float4 ko, vo;
            ko.x = __uint_as_float(f2tf32(kv.x)); ko.y = __uint_as_float(f2tf32(kv.y));
            ko.z = __uint_as_float(f2tf32(kv.z)); ko.w = __uint_as_float(f2tf32(kv.w));
            vo.x = __uint_as_float(f2tf32(vv.x)); vo.y = __uint_as_float(f2tf32(vv.y));
            vo.z = __uint_as_float(f2tf32(vv.z)); vo.w = __uint_as_float(f2tf32(vv.w));
            *(float4*)&Ks[row][col] = ko;
            *(float4*)&Vs[row][col] = vo;
        }
        __syncthreads();

        float sacc[8][4];
        #pragma unroll
        for (int i = 0; i < 8; i++)
            #pragma unroll
            for (int j = 0; j < 4; j++) sacc[i][j] = 0.f;
        #pragma unroll
        for (int ks = 0; ks < 8; ks++) {
            const int kc = ks * 8;
            #pragma unroll
            for (int nt = 0; nt < 8; nt++) {
                unsigned bf[2];
                bf[0] = __float_as_uint(Ks[nt * 8 + g][kc + c]);
                bf[1] = __float_as_uint(Ks[nt * 8 + g][kc + c + 4]);
                mma_tf32(sacc[nt], qf[ks], bf);
            }
        }
        __syncthreads();

        if (t == qt) {
            #pragma unroll
            for (int nt = 0; nt < 8; nt++) {
                const int c0 = nt * 8 + 2 * c, c1 = c0 + 1;
                if (c0 > r0)     sacc[nt][0] = -1e30f;
                if (c1 > r0)     sacc[nt][1] = -1e30f;
                if (c0 > r0 + 8) sacc[nt][2] = -1e30f;
                if (c1 > r0 + 8) sacc[nt][3] = -1e30f;
            }
        }

        float mx0 = m0, mx1 = m1;
        #pragma unroll
        for (int nt = 0; nt < 8; nt++) {
            mx0 = fmaxf(mx0, fmaxf(sacc[nt][0], sacc[nt][1]));
            mx1 = fmaxf(mx1, fmaxf(sacc[nt][2], sacc[nt][3]));
        }
        #pragma unroll
        for (int o = 1; o <= 2; o <<= 1) {
            mx0 = fmaxf(mx0, __shfl_xor_sync(0xffffffffu, mx0, o));
            mx1 = fmaxf(mx1, __shfl_xor_sync(0xffffffffu, mx1, o));
        }
        const float rs0 = __expf(m0 - mx0), rs1 = __expf(m1 - mx1);
        m0 = mx0; m1 = mx1;

        float (*Ps)[68] = Ks;
        float sum0 = 0.f, sum1 = 0.f;
        #pragma unroll
        for (int nt = 0; nt < 8; nt++) {
            const int cc = nt * 8 + 2 * c;
            float p00 = __expf(sacc[nt][0] - mx0);
            float p01 = __expf(sacc[nt][1] - mx0);
            float p10 = __expf(sacc[nt][2] - mx1);
            float p11 = __expf(sacc[nt][3] - mx1);
            sum0 += p00 + p01;
            sum1 += p10 + p11;
            *(float2*)&Ps[r0][cc] = make_float2(
                __uint_as_float(f2tf32(p00)), __uint_as_float(f2tf32(p01)));
            *(float2*)&Ps[r0 + 8][cc] = make_float2(
                __uint_as_float(f2tf32(p10)), __uint_as_float(f2tf32(p11)));
        }
        #pragma unroll
        for (int o = 1; o <= 2; o <<= 1) {
            sum0 += __shfl_xor_sync(0xffffffffu, sum0, o);
            sum1 += __shfl_xor_sync(0xffffffffu, sum1, o);
        }
        l0 = l0 * rs0 + sum0;
        l1 = l1 * rs1 + sum1;
        #pragma unroll
        for (int nt = 0; nt < 8; nt++) {
            oacc[nt][0] *= rs0; oacc[nt][1] *= rs0;
            oacc[nt][2] *= rs1; oacc[nt][3] *= rs1;
        }
        __syncwarp();

        #pragma unroll
        for (int ks = 0; ks < 8; ks++) {
            const int kc = ks * 8;
            unsigned af[4];
            af[0] = __float_as_uint(Ps[r0][kc + c]);
            af[1] = __float_as_uint(Ps[r0 + 8][kc + c]);
            af[2] = __float_as_uint(Ps[r0][kc + c + 4]);
            af[3] = __float_as_uint(Ps[r0 + 8][kc + c + 4]);
            #pragma unroll
            for (int nt = 0; nt < 8; nt++) {
                unsigned bf[2];
                bf[0] = __float_as_uint(Vs[kc + c][nt * 8 + g]);
                bf[1] = __float_as_uint(Vs[kc + c + 4][nt * 8 + g]);
                mma_tf32(oacc[nt], af, bf);
            }
        }
    }

    const float inv0 = 1.0f / l0, inv1 = 1.0f / l1;
    const size_t row0 = (size_t)(b * TSEQ + qbase + r0) * EMB + h * 64;
    const size_t row1 = row0 + (size_t)8 * EMB;
    #pragma unroll
    for (int nt = 0; nt < 8; nt++) {
        const int cc = nt * 8 + 2 * c;
        *(float2*)&out[row0 + cc] = make_float2(
            __uint_as_float(f2tf32(oacc[nt][0] * inv0)),
            __uint_as_float(f2tf32(oacc[nt][1] * inv0)));
        *(float2*)&out[row1 + cc] = make_float2(
            __uint_as_float(f2tf32(oacc[nt][2] * inv1)),
            __uint_as_float(f2tf32(oacc[nt][3] * inv1)));
    }
}

// ---------------------------------------------------------------------------
static float* sym_addr(const void* symbol)
{
    void* p = nullptr;
    cudaGetSymbolAddress(&p, symbol);
    return (float*)p;
}

extern "C" void kernel_launch(void* const* d_in, const int* in_sizes, int n_in,
                              void* d_out, int out_size)
{
    (void)in_sizes; (void)n_in; (void)out_size;
    const float* x      = (const float*)d_in[0];
    const float* Wq     = (const float*)d_in[1];
    const float* bq     = (const float*)d_in[2];
    const float* Wk     = (const float*)d_in[3];
    const float* bk     = (const float*)d_in[4];
    const float* Wv     = (const float*)d_in[5];
    const float* bv     = (const float*)d_in[6];
    const float* Wo     = (const float*)d_in[7];
    const float* bo     = (const float*)d_in[8];
    const float* W1     = (const float*)d_in[9];
    const float* b1     = (const float*)d_in[10];
    const float* W2     = (const float*)d_in[11];
    const float* b2     = (const float*)d_in[12];
    const float* gamma1 = (const float*)d_in[13];
    const float* beta1  = (const float*)d_in[14];
    const float* gamma2 = (const float*)d_in[15];
    const float* beta2  = (const float*)d_in[16];
    float* out = (float*)d_out;

    float* xn   = sym_addr(g_xn);
    float* qb   = sym_addr(g_q);
    float* kb2  = sym_addr(g_k);
    float* vb2  = sym_addr(g_v);
    float* att  = sym_addr(g_att);
    float* x1   = sym_addr(g_x1);
    float* hb   = sym_addr(g_h);
    float* wt   = sym_addr(g_wt);
    float* bqkv = sym_addr(g_bqkv);
    float* wot  = sym_addr(g_wot);
    float* w1t  = sym_addr(g_w1t);
    float* w2t  = sym_addr(g_w2t);

    cudaFuncSetAttribute(tc_gemm<0>, cudaFuncAttributeMaxDynamicSharedMemorySize, SMEM_DYN);
    cudaFuncSetAttribute(tc_gemm<1>, cudaFuncAttributeMaxDynamicSharedMemorySize, SMEM_DYN);
    cudaFuncSetAttribute(tc_gemm<2>, cudaFuncAttributeMaxDynamicSharedMemorySize, SMEM_DYN);

    // 0. weight transposes (+tf32 rounding) and bias pack
    trans_qkv<<<dim3(2, 32, 48), dim3(32, 8)>>>(Wq, Wk, Wv, wt);
    pack_bias<<<12, 256>>>(bq, bk, bv, bqkv);
    trans_w<<<dim3(32, 32),  dim3(32, 8)>>>(Wo, wot, EMB, EMB);
    trans_w<<<dim3(128, 32), dim3(32, 8)>>>(W1, w1t, EMB, DFF);
    trans_w<<<dim3(32, 128), dim3(32, 8)>>>(W2, w2t, DFF, EMB);

    // 1. LN1 (tf32-rounded output)
    ln_kernel<<<MROWS, 256>>>(x, gamma1, beta1, xn);
    // 2. fused QKV projection
    tc_gemm<2><<<dim3(24, 32), 256, SMEM_DYN>>>(
        xn, wt, bqkv, nullptr, qb, kb2, vb2, 3 * EMB, EMB);
    // 3. causal attention -> [B*T, E] (tf32-rounded)
    attn_mma<<<dim3(TSEQ / 64, BATCH * HEADS), 128>>>(qb, kb2, vb2, att);
    // 4. output projection + residual
    tc_gemm<1><<<dim3(8, 32), 256, SMEM_DYN>>>(
        att, wot, bo, x, x1, nullptr, nullptr, EMB, EMB);
    // 5. LN2 (tf32-rounded output)
    ln_kernel<<<MROWS, 256>>>(x1, gamma2, beta2, xn);
    // 6. FFN1 (relu, tf32-rounded output)
    tc_gemm<0><<<dim3(32, 32), 256, SMEM_DYN>>>(
        xn, w1t, b1, nullptr, hb, nullptr, nullptr, DFF, EMB);
    // 7. FFN2 + residual -> out
    tc_gemm<1><<<dim3(8, 32), 256, SMEM_DYN>>>(
        hb, w2t, b2, x1, out, nullptr, nullptr, EMB, DFF);
}

// round 13
// speedup vs baseline: 6.3700x; 1.0112x over previous
#include <cuda_runtime.h>
#include <math.h>
#include <stdint.h>

#define BATCH 2
#define TSEQ  2048
#define EMB   1024
#define HEADS 16
#define DHEAD 64
#define DFF   4096
#define MROWS 4096   // BATCH*TSEQ

// -------- scratch --------
__device__ float g_xn [(size_t)MROWS * EMB];
__device__ float g_q  [(size_t)BATCH * HEADS * TSEQ * DHEAD];
__device__ float g_k  [(size_t)BATCH * HEADS * TSEQ * DHEAD];
__device__ float g_v  [(size_t)BATCH * HEADS * TSEQ * DHEAD];
__device__ float g_att[(size_t)MROWS * EMB];
__device__ float g_x1 [(size_t)MROWS * EMB];
__device__ float g_h  [(size_t)MROWS * DFF];
// transposed (K-major, tf32-rounded) weights
__device__ float g_wt  [(size_t)3 * EMB * EMB];   // [3072][1024] fused QKV
__device__ float g_bqkv[3 * EMB];
__device__ float g_wot [(size_t)EMB * EMB];       // [1024][1024]
__device__ float g_w1t [(size_t)DFF * EMB];       // [4096][1024]
__device__ float g_w2t [(size_t)EMB * DFF];       // [1024][4096]

// ---------------------------------------------------------------------------
// helpers
// ---------------------------------------------------------------------------
__device__ __forceinline__ unsigned f2tf32(float f) {
    unsigned u;
    asm("cvt.rna.tf32.f32 %0, %1;" : "=r"(u) : "f"(f));
    return u;
}
__device__ __forceinline__ void mma_tf32(float* d, const unsigned* a, const unsigned* b) {
    asm volatile(
        "mma.sync.aligned.m16n8k8.row.col.f32.tf32.tf32.f32 "
        "{%0,%1,%2,%3},{%4,%5,%6,%7},{%8,%9},{%0,%1,%2,%3};\n"
        : "+f"(d[0]), "+f"(d[1]), "+f"(d[2]), "+f"(d[3])
        : "r"(a[0]), "r"(a[1]), "r"(a[2]), "r"(a[3]), "r"(b[0]), "r"(b[1]));
}
__device__ __forceinline__ void ldsm4(unsigned* d, uint32_t a) {
    asm volatile("ldmatrix.sync.aligned.m8n8.x4.shared.b16 {%0,%1,%2,%3}, [%4];"
                 : "=r"(d[0]), "=r"(d[1]), "=r"(d[2]), "=r"(d[3]) : "r"(a));
}
__device__ __forceinline__ uint32_t s2u(const void* p) {
    uint32_t a;
    asm("{ .reg .u64 t; cvta.to.shared.u64 t, %1; cvt.u32.u64 %0, t; }"
        : "=r"(a) : "l"(p));
    return a;
}
__device__ __forceinline__ void cpa16(uint32_t dst, const void* src) {
    asm volatile("cp.async.cg.shared.global [%0], [%1], 16;"
                 :: "r"(dst), "l"(src) : "memory");
}
#define CP_COMMIT() asm volatile("cp.async.commit_group;" ::: "memory")
#define CP_WAIT1()  asm volatile("cp.async.wait_group 1;" ::: "memory")
#define CP_WAIT0()  asm volatile("cp.async.wait_group 0;" ::: "memory")

// ---------------------------------------------------------------------------
// LayerNorm — warp per row, 8 rows/block; tf32-rounded output
// ---------------------------------------------------------------------------
__global__ __launch_bounds__(256) void ln_kernel(
    const float* __restrict__ in, const float* __restrict__ gamma,
    const float* __restrict__ beta, float* __restrict__ out)
{
    const int row  = blockIdx.x * 8 + (threadIdx.x >> 5);
    const int lane = threadIdx.x & 31;
    const float* xr = in + (size_t)row * EMB;

    float4 xv[8];
    float s = 0.f;
    #pragma unroll
    for (int i = 0; i < 8; i++) {
        xv[i] = *(const float4*)(xr + (i * 32 + lane) * 4);
        s += xv[i].x + xv[i].y + xv[i].z + xv[i].w;
    }
    #pragma unroll
    for (int o = 16; o > 0; o >>= 1) s += __shfl_xor_sync(0xffffffffu, s, o);
    const float mu = s * (1.0f / EMB);

    float ss = 0.f;
    #pragma unroll
    for (int i = 0; i < 8; i++) {
        xv[i].x -= mu; xv[i].y -= mu; xv[i].z -= mu; xv[i].w -= mu;
        ss += xv[i].x * xv[i].x + xv[i].y * xv[i].y
            + xv[i].z * xv[i].z + xv[i].w * xv[i].w;
    }
    #pragma unroll
    for (int o = 16; o > 0; o >>= 1) ss += __shfl_xor_sync(0xffffffffu, ss, o);
    const float inv = rsqrtf(ss * (1.0f / EMB) + 1e-5f);

    float* orow = out + (size_t)row * EMB;
    #pragma unroll
    for (int i = 0; i < 8; i++) {
        const int cc = (i * 32 + lane) * 4;
        float4 gv = *(const float4*)(gamma + cc);
        float4 bv = *(const float4*)(beta  + cc);
        float4 r;
        r.x = __uint_as_float(f2tf32(xv[i].x * inv * gv.x + bv.x));
        r.y = __uint_as_float(f2tf32(xv[i].y * inv * gv.y + bv.y));
        r.z = __uint_as_float(f2tf32(xv[i].z * inv * gv.z + bv.z));
        r.w = __uint_as_float(f2tf32(xv[i].w * inv * gv.w + bv.w));
        *(float4*)(orow + cc) = r;
    }
}

// ---------------------------------------------------------------------------
// Weight transposes -> K-major [N,K], tf32-pre-rounded
// ---------------------------------------------------------------------------
__global__ void trans_w(const float* __restrict__ in, float* __restrict__ out,
                        int K, int N)
{   // in [K,N] -> out [N,K]; block (32,8), grid (N/32, K/32)
    __shared__ float t[32][33];
    const int n0 = blockIdx.x * 32, k0 = blockIdx.y * 32;
    const int tx = threadIdx.x, ty = threadIdx.y;
    #pragma unroll
    for (int i = 0; i < 32; i += 8)
        t[ty + i][tx] = in[(size_t)(k0 + ty + i) * N + n0 + tx];
    __syncthreads();
    #pragma unroll
    for (int i = 0; i < 32; i += 8)
        out[(size_t)(n0 + ty + i) * K + k0 + tx] =
            __uint_as_float(f2tf32(t[tx][ty + i]));
}

__global__ void trans_qkv(const float* __restrict__ Wq, const float* __restrict__ Wk,
                          const float* __restrict__ Wv, float* __restrict__ out)
{   // W[z][h][E][64] -> out[(z*16+h)*64 + d][e]; grid (2, 32, 48), block (32,8)
    const int zh = blockIdx.z;
    const int z = zh >> 4;
    const float* W = (z == 0 ? Wq : z == 1 ? Wk : Wv) + (size_t)(zh & 15) * EMB * 64;
    __shared__ float t[32][33];
    const int d0 = blockIdx.x * 32, k0 = blockIdx.y * 32;
    const int tx = threadIdx.x, ty = threadIdx.y;
    #pragma unroll
    for (int i = 0; i < 32; i += 8)
        t[ty + i][tx] = W[(size_t)(k0 + ty + i) * 64 + d0 + tx];
    __syncthreads();
    float* o = out + (size_t)zh * 64 * EMB;
    #pragma unroll
    for (int i = 0; i < 32; i += 8)
        o[(size_t)(d0 + ty + i) * EMB + k0 + tx] =
            __uint_as_float(f2tf32(t[tx][ty + i]));
}

__global__ void pack_bias(const float* __restrict__ bq, const float* __restrict__ bk,
                          const float* __restrict__ bv, float* __restrict__ o)
{
    const int n = blockIdx.x * 256 + threadIdx.x;
    const float* b = n < 1024 ? bq : n < 2048 ? bk : bv;
    o[n] = b[n & 1023];
}

// ---------------------------------------------------------------------------
// TF32 mma.sync GEMM: cp.async 3-stage pipeline + ldmatrix (unchanged R12)
// MODE 0: relu(acc+bias) tf32; MODE 1: resid+acc+bias; MODE 2: QKV scatter tf32
// ---------------------------------------------------------------------------
#define STAGE_BYTES 32768
#define NSTAGE 3
#define SMEM_DYN (NSTAGE * STAGE_BYTES)

template<int MODE>
__global__ __launch_bounds__(256) void tc_gemm(
    const float* __restrict__ A, const float* __restrict__ Bt,
    const float* __restrict__ bias, const float* __restrict__ resid,
    float* __restrict__ C0, float* __restrict__ C1, float* __restrict__ C2,
    int N, int K)
{
    extern __shared__ char smem[];
    const uint32_t sb = s2u(smem);
    const int tid = threadIdx.x;
    const int lane = tid & 31, warp = tid >> 5;
    const int warpM = warp & 1, warpN = warp >> 1;
    const int lane7 = lane & 7;
    const int bm = blockIdx.y * 128, bn = blockIdx.x * 128;

    float acc[64];
    #pragma unroll
    for (int i = 0; i < 64; i++) acc[i] = 0.f;

    int rowA[4], chA[4];
    #pragma unroll
    for (int j = 0; j < 4; j++) {
        const int idx = j * 256 + tid;
        rowA[j] = idx >> 3;
        chA[j]  = idx & 7;
    }

    auto issue = [&](int t, int buf) {
        const int k0 = t << 5;
        const uint32_t base = sb + buf * STAGE_BYTES;
        #pragma unroll
        for (int j = 0; j < 4; j++) {
            const int row = rowA[j], ch = chA[j];
            const uint32_t off = row * 128 + ((ch ^ (row & 7)) << 4);
            cpa16(base + off,          A  + (size_t)(bm + row) * K + k0 + ch * 4);
            cpa16(base + 16384 + off,  Bt + (size_t)(bn + row) * K + k0 + ch * 4);
        }
        CP_COMMIT();
    };

    const int a_row_base = warpM * 64 + lane7 + ((lane >> 3) & 1) * 8;
    const int a_ch_sel   = lane >> 4;
    const int b_msel     = lane >> 3;
    const int b_row_base = warpN * 32 + (b_msel >> 1) * 8 + lane7;
    const int b_ch_sel   = b_msel & 1;

    const int nk = K >> 5;
    issue(0, 0);
    issue(1, 1);

    for (int t = 0; t < nk; ++t) {
        const int buf = t % NSTAGE;
        if (t + 2 < nk) { CP_WAIT1(); } else { CP_WAIT0(); }
        __syncthreads();
        if (t + 2 < nk) issue(t + 2, (t + 2) % NSTAGE);

        const uint32_t ab = sb + buf * STAGE_BYTES;
        const uint32_t bb = ab + 16384;
        const uint32_t aBase = ab + a_row_base * 128;

        #pragma unroll
        for (int ks = 0; ks < 4; ++ks) {
            unsigned af[4][4], bf[4][2];
            #pragma unroll
            for (int mt = 0; mt < 4; mt++) {
                const uint32_t addr = aBase + mt * 2048 +
                    ((uint32_t)((2 * ks + a_ch_sel) ^ lane7) << 4);
                ldsm4(af[mt], addr);
            }
            #pragma unroll
            for (int j = 0; j < 2; j++) {
                unsigned d[4];
                const uint32_t addr = bb + (b_row_base + j * 16) * 128 +
                    ((uint32_t)((2 * ks + b_ch_sel) ^ lane7) << 4);
                ldsm4(d, addr);
                bf[2 * j][0]     = d[0]; bf[2 * j][1]     = d[1];
                bf[2 * j + 1][0] = d[2]; bf[2 * j + 1][1] = d[3];
            }
            #pragma unroll
            for (int mt = 0; mt < 4; mt++)
                #pragma unroll
                for (int nt = 0; nt < 4; nt++)
                    mma_tf32(&acc[(mt * 4 + nt) * 4], af[mt], bf[nt]);
        }
    }

    const int g = lane >> 2, c = lane & 3;
    #pragma unroll
    for (int mt = 0; mt < 4; mt++) {
        const int r0 = bm + warpM * 64 + mt * 16 + g;
        const int r1 = r0 + 8;
        #pragma unroll
        for (int nt = 0; nt < 4; nt++) {
            const int nn = bn + warpN * 32 + nt * 8 + 2 * c;
            const float* a = &acc[(mt * 4 + nt) * 4];
            float2 bb2 = *(const float2*)&bias[nn];
            float v00 = a[0] + bb2.x, v01 = a[1] + bb2.y;
            float v10 = a[2] + bb2.x, v11 = a[3] + bb2.y;
            if (MODE == 0) {
                v00 = __uint_as_float(f2tf32(fmaxf(v00, 0.f)));
                v01 = __uint_as_float(f2tf32(fmaxf(v01, 0.f)));
                v10 = __uint_as_float(f2tf32(fmaxf(v10, 0.f)));
                v11 = __uint_as_float(f2tf32(fmaxf(v11, 0.f)));
                *(float2*)&C0[(size_t)r0 * N + nn] = make_float2(v00, v01);
                *(float2*)&C0[(size_t)r1 * N + nn] = make_float2(v10, v11);
            } else if (MODE == 1) {
                float2 rr0 = *(const float2*)&resid[(size_t)r0 * N + nn];
                float2 rr1 = *(const float2*)&resid[(size_t)r1 * N + nn];
                *(float2*)&C0[(size_t)r0 * N + nn] = make_float2(v00 + rr0.x, v01 + rr0.y);
                *(float2*)&C0[(size_t)r1 * N + nn] = make_float2(v10 + rr1.x, v11 + rr1.y);
            } else {
                // QKV scatter, tf32-rounded (consumed by attention mma only)
                v00 = __uint_as_float(f2tf32(v00));
                v01 = __uint_as_float(f2tf32(v01));
                v10 = __uint_as_float(f2tf32(v10));
                v11 = __uint_as_float(f2tf32(v11));
                const int z = nn >> 10;
                float* O = (z == 0) ? C0 : (z == 1) ? C1 : C2;
                const int h = (nn & 1023) >> 6, d = nn & 63;
                const int b0 = r0 >> 11, t0i = r0 & 2047;
                const int b1 = r1 >> 11, t1i = r1 & 2047;
                *(float2*)&O[((((size_t)(b0 * HEADS + h)) * TSEQ + t0i) << 6) + d] =
                    make_float2(v00, v01);
                *(float2*)&O[((((size_t)(b1 * HEADS + h)) * TSEQ + t1i) << 6) + d] =
                    make_float2(v10, v11);
            }
        }
    }
}

// ---------------------------------------------------------------------------
// TF32 causal flash attention: q-tile 128, 256 threads (8 warps x m16),
// kv tiles 64, cp.async loads (q/k/v pre-rounded tf32), P in own smem.
// Dynamic smem: Ks[64][68] + Vs[64][68] + Ps[128][68] = 68KB.
// ---------------------------------------------------------------------------
#define ATTN_SMEM ((64 + 64 + 128) * 68 * 4)

__global__ __launch_bounds__(256) void attn_mma(
    const float* __restrict__ q, const float* __restrict__ k,
    const float* __restrict__ v, float* __restrict__ out)
{
    extern __shared__ float sm[];
    float (*Ks)[68] = (float(*)[68])sm;
    float (*Vs)[68] = (float(*)[68])(sm + 64 * 68);
    float (*Ps)[68] = (float(*)[68])(sm + 128 * 68);

    const int bh = blockIdx.y;
    const int b = bh >> 4, h = bh & 15;
    const int qt = gridDim.x - 1 - blockIdx.x;   // heavy tiles first
    const int qbase = qt * 128;
    const float* Q  = q + (size_t)bh * TSEQ * DHEAD;
    const float* Kp = k + (size_t)bh * TSEQ * DHEAD;
    const float* Vp = v + (size_t)bh * TSEQ * DHEAD;

    const int tid = threadIdx.x;
    const int lane = tid & 31, w = tid >> 5;
    const int g = lane >> 2, c = lane & 3;
    const int r0 = w * 16 + g;                    // local rows r0, r0+8

    // Q fragments: values already tf32; x0.125 is exact
    unsigned qf[8][4];
    #pragma unroll
    for (int ks = 0; ks < 8; ks++) {
        const int kc = ks * 8;
        qf[ks][0] = __float_as_uint(0.125f * Q[(size_t)(qbase + r0)     * 64 + kc + c]);
        qf[ks][1] = __float_as_uint(0.125f * Q[(size_t)(qbase + r0 + 8) * 64 + kc + c]);
        qf[ks][2] = __float_as_uint(0.125f * Q[(size_t)(qbase + r0)     * 64 + kc + c + 4]);
        qf[ks][3] = __float_as_uint(0.125f * Q[(size_t)(qbase + r0 + 8) * 64 + kc + c + 4]);
    }

    float oacc[8][4];
    #pragma unroll
    for (int i = 0; i < 8; i++)
        #pragma unroll
        for (int j = 0; j < 4; j++) oacc[i][j] = 0.f;
    float m0 = -1e30f, m1 = -1e30f, l0 = 0.f, l1 = 0.f;

    const int ntiles = 2 * qt + 2;
    for (int t = 0; t < ntiles; t++) {
        const int kb = t * 64;
        __syncthreads();   // prior Ks/Vs reads done
        // cp.async K,V: 64x64 floats each; 4 chunks of 16B per thread each
        #pragma unroll
        for (int j = 0; j < 4; j++) {
            const int idx = j * 256 + tid;            // 0..1023
            const int row = idx >> 4, col = (idx & 15) << 2;
            cpa16(s2u(&Ks[row][col]), &Kp[(size_t)(kb + row) * 64 + col]);
            cpa16(s2u(&Vs[row][col]), &Vp[(size_t)(kb + row) * 64 + col]);
        }
        CP_COMMIT();
        CP_WAIT0();
        __syncthreads();

        // S = Q @ K^T
        float sacc[8][4];
        #pragma unroll
        for (int i = 0; i < 8; i++)
            #pragma unroll
            for (int j = 0; j < 4; j++) sacc[i][j] = 0.f;
        #pragma unroll
        for (int ks = 0; ks < 8; ks++) {
            const int kc = ks * 8;
            #pragma unroll
            for (int nt = 0; nt < 8; nt++) {
                unsigned bf[2];
                bf[0] = __float_as_uint(Ks[nt * 8 + g][kc + c]);
                bf[1] = __float_as_uint(Ks[nt * 8 + g][kc + c + 4]);
                mma_tf32(sacc[nt], qf[ks], bf);
            }
        }

        // causal mask (only last two tiles can cross the diagonal)
        if (t >= ntiles - 2) {
            const int rg0 = qbase + r0, rg1 = rg0 + 8;
            #pragma unroll
            for (int nt = 0; nt < 8; nt++) {
                const int c0 = kb + nt * 8 + 2 * c, c1 = c0 + 1;
                if (c0 > rg0) sacc[nt][0] = -1e30f;
                if (c1 > rg0) sacc[nt][1] = -1e30f;
                if (c0 > rg1) sacc[nt][2] = -1e30f;
                if (c1 > rg1) sacc[nt][3] = -1e30f;
            }
        }

        // online softmax (rows r0, r0+8), quad reduction
        float mx0 = m0, mx1 = m1;
        #pragma unroll
        for (int nt = 0; nt < 8; nt++) {
            mx0 = fmaxf(mx0, fmaxf(sacc[nt][0], sacc[nt][1]));
            mx1 = fmaxf(mx1, fmaxf(sacc[nt][2], sacc[nt][3]));
        }
        #pragma unroll
        for (int o = 1; o <= 2; o <<= 1) {
            mx0 = fmaxf(mx0, __shfl_xor_sync(0xffffffffu, mx0, o));
            mx1 = fmaxf(mx1, __shfl_xor_sync(0xffffffffu, mx1, o));
        }
        const float rs0 = __expf(m0 - mx0), rs1 = __expf(m1 - mx1);
        m0 = mx0; m1 = mx1;

        float sum0 = 0.f, sum1 = 0.f;
        #pragma unroll
        for (int nt = 0; nt < 8; nt++) {
            const int cc = nt * 8 + 2 * c;
            float p00 = __expf(sacc[nt][0] - mx0);
            float p01 = __expf(sacc[nt][1] - mx0);
            float p10 = __expf(sacc[nt][2] - mx1);
            float p11 = __expf(sacc[nt][3] - mx1);
            sum0 += p00 + p01;
            sum1 += p10 + p11;
            *(float2*)&Ps[r0][cc] = make_float2(
                __uint_as_float(f2tf32(p00)), __uint_as_float(f2tf32(p01)));
            *(float2*)&Ps[r0 + 8][cc] = make_float2(
                __uint_as_float(f2tf32(p10)), __uint_as_float(f2tf32(p11)));
        }
        #pragma unroll
        for (int o = 1; o <= 2; o <<= 1) {
            sum0 += __shfl_xor_sync(0xffffffffu, sum0, o);
            sum1 += __shfl_xor_sync(0xffffffffu, sum1, o);
        }
        l0 = l0 * rs0 + sum0;
        l1 = l1 * rs1 + sum1;
        #pragma unroll
        for (int nt = 0; nt < 8; nt++) {
            oacc[nt][0] *= rs0; oacc[nt][1] *= rs0;
            oacc[nt][2] *= rs1; oacc[nt][3] *= rs1;
        }
        __syncwarp();   // own Ps rows visible to own warp

        // O += P @ V
        #pragma unroll
        for (int ks = 0; ks < 8; ks++) {
            const int kc = ks * 8;
            unsigned af[4];
            af[0] = __float_as_uint(Ps[r0][kc + c]);
            af[1] = __float_as_uint(Ps[r0 + 8][kc + c]);
            af[2] = __float_as_uint(Ps[r0][kc + c + 4]);
            af[3] = __float_as_uint(Ps[r0 + 8][kc + c + 4]);
            #pragma unroll
            for (int nt = 0; nt < 8; nt++) {
                unsigned bf[2];
                bf[0] = __float_as_uint(Vs[kc + c][nt * 8 + g]);
                bf[1] = __float_as_uint(Vs[kc + c + 4][nt * 8 + g]);
                mma_tf32(oacc[nt], af, bf);
            }
        }
    }

    // normalize + write concat layout [B*T, E], tf32-rounded (feeds Wo GEMM)
    const float inv0 = 1.0f / l0, inv1 = 1.0f / l1;
    const size_t row0 = (size_t)(b * TSEQ + qbase + r0) * EMB + h * 64;
    const size_t row1 = row0 + (size_t)8 * EMB;
    #pragma unroll
    for (int nt = 0; nt < 8; nt++) {
        const int cc = nt * 8 + 2 * c;
        *(float2*)&out[row0 + cc] = make_float2(
            __uint_as_float(f2tf32(oacc[nt][0] * inv0)),
            __uint_as_float(f2tf32(oacc[nt][1] * inv0)));
        *(float2*)&out[row1 + cc] = make_float2(
            __uint_as_float(f2tf32(oacc[nt][2] * inv1)),
            __uint_as_float(f2tf32(oacc[nt][3] * inv1)));
    }
}

// ---------------------------------------------------------------------------
static float* sym_addr(const void* symbol)
{
    void* p = nullptr;
    cudaGetSymbolAddress(&p, symbol);
    return (float*)p;
}

extern "C" void kernel_launch(void* const* d_in, const int* in_sizes, int n_in,
                              void* d_out, int out_size)
{
    (void)in_sizes; (void)n_in; (void)out_size;
    const float* x      = (const float*)d_in[0];
    const float* Wq     = (const float*)d_in[1];
    const float* bq     = (const float*)d_in[2];
    const float* Wk     = (const float*)d_in[3];
    const float* bk     = (const float*)d_in[4];
    const float* Wv     = (const float*)d_in[5];
    const float* bv     = (const float*)d_in[6];
    const float* Wo     = (const float*)d_in[7];
    const float* bo     = (const float*)d_in[8];
    const float* W1     = (const float*)d_in[9];
    const float* b1     = (const float*)d_in[10];
    const float* W2     = (const float*)d_in[11];
    const float* b2     = (const float*)d_in[12];
    const float* gamma1 = (const float*)d_in[13];
    const float* beta1  = (const float*)d_in[14];
    const float* gamma2 = (const float*)d_in[15];
    const float* beta2  = (const float*)d_in[16];
    float* out = (float*)d_out;

    float* xn   = sym_addr(g_xn);
    float* qb   = sym_addr(g_q);
    float* kb2  = sym_addr(g_k);
    float* vb2  = sym_addr(g_v);
    float* att  = sym_addr(g_att);
    float* x1   = sym_addr(g_x1);
    float* hb   = sym_addr(g_h);
    float* wt   = sym_addr(g_wt);
    float* bqkv = sym_addr(g_bqkv);
    float* wot  = sym_addr(g_wot);
    float* w1t  = sym_addr(g_w1t);
    float* w2t  = sym_addr(g_w2t);

    cudaFuncSetAttribute(tc_gemm<0>, cudaFuncAttributeMaxDynamicSharedMemorySize, SMEM_DYN);
    cudaFuncSetAttribute(tc_gemm<1>, cudaFuncAttributeMaxDynamicSharedMemorySize, SMEM_DYN);
    cudaFuncSetAttribute(tc_gemm<2>, cudaFuncAttributeMaxDynamicSharedMemorySize, SMEM_DYN);
    cudaFuncSetAttribute(attn_mma,  cudaFuncAttributeMaxDynamicSharedMemorySize, ATTN_SMEM);

    // 0. weight transposes (+tf32 rounding) and bias pack
    trans_qkv<<<dim3(2, 32, 48), dim3(32, 8)>>>(Wq, Wk, Wv, wt);
    pack_bias<<<12, 256>>>(bq, bk, bv, bqkv);
    trans_w<<<dim3(32, 32),  dim3(32, 8)>>>(Wo, wot, EMB, EMB);
    trans_w<<<dim3(128, 32), dim3(32, 8)>>>(W1, w1t, EMB, DFF);
    trans_w<<<dim3(32, 128), dim3(32, 8)>>>(W2, w2t, DFF, EMB);

    // 1. LN1 (tf32-rounded output)
    ln_kernel<<<MROWS / 8, 256>>>(x, gamma1, beta1, xn);
    // 2. fused QKV projection (tf32-rounded outputs)
    tc_gemm<2><<<dim3(24, 32), 256, SMEM_DYN>>>(
        xn, wt, bqkv, nullptr, qb, kb2, vb2, 3 * EMB, EMB);
    // 3. causal attention, q-tile 128 -> [B*T, E]
    attn_mma<<<dim3(TSEQ / 128, BATCH * HEADS), 256, ATTN_SMEM>>>(qb, kb2, vb2, att);
    // 4. output projection + residual
    tc_gemm<1><<<dim3(8, 32), 256, SMEM_DYN>>>(
        att, wot, bo, x, x1, nullptr, nullptr, EMB, EMB);
    // 5. LN2 (tf32-rounded output)
    ln_kernel<<<MROWS / 8, 256>>>(x1, gamma2, beta2, xn);
    // 6. FFN1 (relu, tf32-rounded output)
    tc_gemm<0><<<dim3(32, 32), 256, SMEM_DYN>>>(
        xn, w1t, b1, nullptr, hb, nullptr, nullptr, DFF, EMB);
    // 7. FFN2 + residual -> out
    tc_gemm<1><<<dim3(8, 32), 256, SMEM_DYN>>>(
        hb, w2t, b2, x1, out, nullptr, nullptr, EMB, DFF);
}